// round 12
// baseline (speedup 1.0000x reference)
#include <cuda_runtime.h>
#include <cuda_bf16.h>

#define NTOK 2048
#define HD   512
#define NH   8
#define DH   64
#define MB   4096
#define SBN  512
#define NWID 729

// ---------------- scratch ----------------
__device__ float g_q[NTOK*HD], g_kf[NTOK*HD], g_vf[NTOK*HD];
__device__ float g_ck[MB*HD], g_cv[MB*HD];
__device__ float g_P8[(size_t)NTOK*MB];
__device__ float g_invl[NH*NTOK];
__device__ float g_rowm[NH*NTOK];
__device__ float g_outc[NTOK*HD], g_outs[NTOK*HD], g_outw[NTOK*HD];
__device__ float g_gate[NTOK*3];
__device__ int g_cnt[MB], g_boff[MB+1], g_bperm[NTOK], g_bid[NTOK];
__device__ int g_sbcnt[SBN], g_sboff[SBN+1], g_sbperm[NTOK], g_sbid[NTOK];
__device__ int g_wcnt[NWID], g_woff[NWID+1], g_wperm[NTOK], g_wid[NTOK];
__device__ int g_scount[SBN], g_soff[SBN+1], g_slist[MB], g_sidc[MB];
__device__ int g_vlist[MB], g_nvalid;
__device__ int g_pei[NTOK], g_packed[NTOK];
__device__ int g_r1[NTOK], g_r2[NTOK], g_r3[NTOK], g_rs[MB];
// split-bf16 operands
__device__ __nv_bfloat16 g_wth[6*HD*HD], g_wtl[6*HD*HD];
__device__ __nv_bfloat16 g_fh[NTOK*HD], g_fl[NTOK*HD];
__device__ __nv_bfloat16 g_qh[NTOK*HD], g_ql[NTOK*HD];   // pre-scaled by 0.125
__device__ __nv_bfloat16 g_kah[MB*HD], g_kal[MB*HD], g_vah[MB*HD], g_val[MB*HD];
__device__ __nv_bfloat16 g_ckh[MB*HD], g_ckl[MB*HD];
__device__ __nv_bfloat16 g_cvth[NH*DH*MB], g_cvtl[NH*DH*MB];

// ---------------- helpers ----------------
__device__ __forceinline__ unsigned smem_u32(const void* p){
    unsigned a;
    asm("{ .reg .u64 t; cvta.to.shared.u64 t, %1; cvt.u32.u64 %0, t; }" : "=r"(a) : "l"(p));
    return a;
}
__device__ __forceinline__ void sts128(unsigned a, float4 v){
    asm volatile("st.shared.v4.b32 [%0], {%1,%2,%3,%4};" :: "r"(a),
        "r"(__float_as_uint(v.x)), "r"(__float_as_uint(v.y)),
        "r"(__float_as_uint(v.z)), "r"(__float_as_uint(v.w)) : "memory");
}
__device__ __forceinline__ void cpa16(unsigned dst, const void* src){
    asm volatile("cp.async.cg.shared.global [%0], [%1], 16;" :: "r"(dst), "l"(src) : "memory");
}
#define CP_COMMIT() asm volatile("cp.async.commit_group;" ::: "memory")
#define CP_WAIT0()  asm volatile("cp.async.wait_group 0;" ::: "memory")
#define CP_WAIT1()  asm volatile("cp.async.wait_group 1;" ::: "memory")
#define CP_WAIT2()  asm volatile("cp.async.wait_group 2;" ::: "memory")
__device__ __forceinline__ void ldsm4(unsigned* r, unsigned addr){
    asm volatile("ldmatrix.sync.aligned.m8n8.x4.shared.b16 {%0,%1,%2,%3}, [%4];"
        : "=r"(r[0]), "=r"(r[1]), "=r"(r[2]), "=r"(r[3]) : "r"(addr));
}
__device__ __forceinline__ void mma16816(float* c, const unsigned* a, const unsigned* b){
    asm volatile("mma.sync.aligned.m16n8k16.row.col.f32.bf16.bf16.f32 "
        "{%0,%1,%2,%3}, {%4,%5,%6,%7}, {%8,%9}, {%0,%1,%2,%3};"
        : "+f"(c[0]), "+f"(c[1]), "+f"(c[2]), "+f"(c[3])
        : "r"(a[0]), "r"(a[1]), "r"(a[2]), "r"(a[3]), "r"(b[0]), "r"(b[1]));
}
__device__ __forceinline__ float fexp(float x){
    x = fminf(fmaxf(x, -87.0f), 88.0f);
    float y = x * 1.4426950408889634f;
    float z = y + 12582912.0f;
    int ki = __float_as_int(z) - 0x4B400000;
    float f = y - (z - 12582912.0f);
    float p = 1.5403530393381609e-4f;
    p = fmaf(p, f, 1.3333558146428443e-3f);
    p = fmaf(p, f, 9.6181291076284772e-3f);
    p = fmaf(p, f, 5.5504108664821580e-2f);
    p = fmaf(p, f, 2.4022650695910071e-1f);
    p = fmaf(p, f, 6.9314718055994531e-1f);
    p = fmaf(p, f, 1.0f);
    return __int_as_float((ki + 127) << 23) * p;
}
__device__ __forceinline__ unsigned pack2(__nv_bfloat16 a, __nv_bfloat16 b){
    return ((unsigned)__bfloat16_as_ushort(b) << 16) | __bfloat16_as_ushort(a);
}

// ---------------- setup ----------------
__global__ void zero_k(){
    int i = blockIdx.x*256 + threadIdx.x;
    if (i < MB){ g_cnt[i] = 0; g_rs[i] = 0; }
    if (i < SBN){ g_sbcnt[i] = 0; g_scount[i] = 0; }
    if (i < NWID) g_wcnt[i] = 0;
    if (i < NTOK){ g_r1[i] = 0; g_r2[i] = 0; g_r3[i] = 0; }
}
__global__ void prep_k(const int* __restrict__ coords){
    int t = blockIdx.x*256 + threadIdx.x;
    if (t >= NTOK) return;
    int cf = coords[t];
    int x = cf >> 12, y = (cf >> 6) & 63, z = cf & 63;
    int bid = ((x>>2)<<8) | ((y>>2)<<4) | (z>>2);
    g_bid[t] = bid; atomicAdd(&g_cnt[bid], 1);
    int sb = ((x>>3)<<6) | ((y>>3)<<3) | (z>>3);
    g_sbid[t] = sb; atomicAdd(&g_sbcnt[sb], 1);
    int wd = (((x+4)>>3)*9 + ((y+4)>>3))*9 + ((z+4)>>3);
    g_wid[t] = wd; atomicAdd(&g_wcnt[wd], 1);
    g_pei[t] = (((x&3)*4 + (y&3))*4 + (z&3)) * HD;
    g_packed[t] = bid | (sb << 12) | (wd << 21);
}
// merged: convW (blocks 0..1535) + convA (1536..5631) + gate (5632..6655)
__global__ void init2_k(const float* __restrict__ feats,
    const float* W0, const float* W1, const float* W2,
    const float* W3, const float* W4, const float* W5,
    const float* __restrict__ Wg){
    __shared__ float t[32][33];
    int bid = blockIdx.x, tid = threadIdx.x;
    if (bid < 1536){
        int z = bid >> 8, rem = bid & 255;
        int bn = (rem & 15)*32, bk = (rem >> 4)*32;
        const float* W = z==0?W0 : z==1?W1 : z==2?W2 : z==3?W3 : z==4?W4 : W5;
        __nv_bfloat16* h = g_wth + (size_t)z*HD*HD;
        __nv_bfloat16* l = g_wtl + (size_t)z*HD*HD;
        int tx = tid & 31, ty = tid >> 5;
        for (int r = ty; r < 32; r += 8) t[r][tx] = W[(size_t)(bk+r)*HD + bn + tx];
        __syncthreads();
        for (int r = ty; r < 32; r += 8){
            float x = t[tx][r];
            __nv_bfloat16 hb = __float2bfloat16(x);
            h[(size_t)(bn+r)*HD + bk + tx] = hb;
            l[(size_t)(bn+r)*HD + bk + tx] = __float2bfloat16(x - __bfloat162float(hb));
        }
    } else if (bid < 5632){
        int i = (bid - 1536)*256 + tid;
        float x = feats[i];
        __nv_bfloat16 hb = __float2bfloat16(x);
        g_fh[i] = hb; g_fl[i] = __float2bfloat16(x - __bfloat162float(hb));
    } else {
        int n = (bid - 5632)*2 + (tid >> 7);
        int sub = tid & 127, w = sub >> 5, lane = sub & 31;
        if (w < 3){
            float s = 0.f;
            for (int i = lane; i < HD; i += 32) s += feats[n*HD + i] * Wg[i*3 + w];
            #pragma unroll
            for (int o = 16; o; o >>= 1) s += __shfl_xor_sync(0xffffffffu, s, o);
            if (lane == 0) g_gate[n*3 + w] = 1.0f / (1.0f + fexp(-s));
        }
    }
}
__device__ __forceinline__ void warp_exscan(const int* cnt, int* off, int len){
    int lane = threadIdx.x & 31;
    int run = 0;
    for (int base = 0; base < len; base += 32){
        int raw = (base+lane < len) ? cnt[base+lane] : 0;
        int v = raw;
        #pragma unroll
        for (int o = 1; o < 32; o <<= 1){ int t = __shfl_up_sync(0xffffffffu, v, o); if (lane >= o) v += t; }
        if (base+lane < len) off[base+lane] = run + v - raw;
        run += __shfl_sync(0xffffffffu, v, 31);
    }
    if (lane == 0) off[len] = run;
}
__global__ void scan1_k(){
    int w = threadIdx.x >> 5;
    if (w == 0) warp_exscan(g_cnt, g_boff, MB);
    else if (w == 1) warp_exscan(g_sbcnt, g_sboff, SBN);
    else if (w == 2) warp_exscan(g_wcnt, g_woff, NWID);
    else {
        int lane = threadIdx.x & 31;
        int run = 0;
        for (int base = 0; base < MB; base += 32){
            int valid = g_cnt[base+lane] > 0 ? 1 : 0;
            int v = valid;
            #pragma unroll
            for (int o = 1; o < 32; o <<= 1){ int t = __shfl_up_sync(0xffffffffu, v, o); if (lane >= o) v += t; }
            if (valid) g_vlist[run + v - 1] = base + lane;
            run += __shfl_sync(0xffffffffu, v, 31);
        }
        if (lane == 0) g_nvalid = run;
    }
}
__global__ void scan2_k(){ warp_exscan(g_scount, g_soff, SBN); }

__global__ void permcnt_k(){
    int bt = blockIdx.x, bu = blockIdx.y;
    if (bu > bt) return;
    __shared__ int sp[256];
    int tid = threadIdx.x;
    int t = bt*256 + tid;
    sp[tid] = g_packed[bu*256 + tid];
    __syncthreads();
    int my = g_packed[t];
    int lim = (bu < bt) ? 256 : tid;
    int r1 = 0, r2 = 0, r3 = 0;
    for (int u = 0; u < lim; u++){
        int p = sp[u] ^ my;
        r3 += ((p & 0x00000FFF) == 0);
        r1 += ((p & 0x001FF000) == 0);
        r2 += ((p & 0x7FE00000) == 0);
    }
    if (r1) atomicAdd(&g_r1[t], r1);
    if (r2) atomicAdd(&g_r2[t], r2);
    if (r3) atomicAdd(&g_r3[t], r3);
}
__global__ void permscat_k(){
    int t = blockIdx.x*256 + threadIdx.x;
    if (t >= NTOK) return;
    int my = g_packed[t];
    int bd = my & 0xFFF, sb = (my >> 12) & 0x1FF, wd = (my >> 21) & 0x3FF;
    g_sbperm[g_sboff[sb] + g_r1[t]] = t;
    g_wperm [g_woff[wd]  + g_r2[t]] = t;
    g_bperm [g_boff[bd]  + g_r3[t]] = t;
}
__global__ void scnt_k(){
    int bj = blockIdx.x, bu = blockIdx.y;
    if (bu > bj) return;
    __shared__ int sp[256];
    int tid = threadIdx.x;
    int nv = g_nvalid;
    int ju = bu*256 + tid;
    sp[tid] = (ju < nv) ? g_sidc[ju] : -1;
    __syncthreads();
    int j = bj*256 + tid;
    if (j >= nv) return;
    int my = g_sidc[j];
    int lim = (bu < bj) ? 256 : tid;
    int r = 0;
    for (int u = 0; u < lim; u++) r += (sp[u] == my);
    if (r) atomicAdd(&g_rs[j], r);
}
__global__ void sscat_k(){
    int j = blockIdx.x*256 + threadIdx.x;
    if (j >= g_nvalid) return;
    g_slist[g_soff[g_sidc[j]] + g_rs[j]] = j;
}

__global__ void avg_k(const float* __restrict__ pe){
    int j = blockIdx.x;
    int nv = g_nvalid;
    if (j >= nv){
        __nv_bfloat16 zb = __float2bfloat16(0.f);
        for (int c = threadIdx.x; c < HD; c += 256){
            g_kah[j*HD+c]=zb; g_kal[j*HD+c]=zb; g_vah[j*HD+c]=zb; g_val[j*HD+c]=zb;
        }
        return;
    }
    int m = g_vlist[j];
    int c0 = g_boff[m], c1 = g_boff[m+1];
    float dn = 1.0f / (float)max(c1 - c0, 1);
    for (int c = threadIdx.x; c < HD; c += 256){
        float sk = 0.f, sv = 0.f;
        for (int i = c0; i < c1; i++){
            int t = g_bperm[i];
            sk += g_kf[t*HD + c] + pe[g_pei[t] + c];
            sv += g_vf[t*HD + c];
        }
        sk *= dn; sv *= dn;
        __nv_bfloat16 kh = __float2bfloat16(sk);
        __nv_bfloat16 vh = __float2bfloat16(sv);
        g_kah[j*HD+c] = kh; g_kal[j*HD+c] = __float2bfloat16(sk - __bfloat162float(kh));
        g_vah[j*HD+c] = vh; g_val[j*HD+c] = __float2bfloat16(sv - __bfloat162float(vh));
    }
    if (threadIdx.x == 0){
        int mx = m >> 8, my = (m >> 4) & 15, mz = m & 15;
        g_sidc[j] = ((mx>>1)<<6) | ((my>>1)<<3) | (mz>>1);
        atomicAdd(&g_scount[g_sidc[j]], 1);
    }
}
__global__ void cvt_k(){
    __shared__ float t[32][33];
    int bj = blockIdx.x*32, bd = blockIdx.y*32;
    int tx = threadIdx.x & 31, ty = threadIdx.x >> 5;
    for (int r = ty; r < 32; r += 8) t[r][tx] = g_cv[(size_t)(bj+r)*HD + bd + tx];
    __syncthreads();
    for (int r = ty; r < 32; r += 8){
        int gd = bd + r, h = gd >> 6, dd = gd & 63;
        float x = t[tx][r];
        __nv_bfloat16 hb = __float2bfloat16(x);
        g_cvth[(size_t)(h*DH + dd)*MB + bj + tx] = hb;
        g_cvtl[(size_t)(h*DH + dd)*MB + bj + tx] = __float2bfloat16(x - __bfloat162float(hb));
    }
}

// ---------------- mma.sync stage compute: 8 warps, CTA tile 128x128 ----------------
#define KSTR 24
#define ARR  6144
#define STG  24576
#define MMSM (4*STG)

__device__ __forceinline__ void mma_stage(unsigned base, int wm, int wn, int lane, float acc[4][4][4]){
    unsigned ah[4][4], al[4][4], bh[4][2], bl[4][2];
    int t7 = lane & 7, t8 = lane >> 3;
    #pragma unroll
    for (int mt = 0; mt < 4; mt++){
        int m = wm*64 + mt*16 + (t8&1)*8 + t7;
        unsigned off = base + (m*KSTR + (t8>>1)*8)*2;
        ldsm4(ah[mt], off);
        ldsm4(al[mt], off + ARR);
    }
    #pragma unroll
    for (int p = 0; p < 2; p++){
        int n = wn*32 + p*16 + (t8>>1)*8 + t7;
        unsigned off = base + 2*ARR + (n*KSTR + (t8&1)*8)*2;
        unsigned r[4];
        ldsm4(r, off);
        bh[2*p][0]=r[0]; bh[2*p][1]=r[1]; bh[2*p+1][0]=r[2]; bh[2*p+1][1]=r[3];
        ldsm4(r, off + ARR);
        bl[2*p][0]=r[0]; bl[2*p][1]=r[1]; bl[2*p+1][0]=r[2]; bl[2*p+1][1]=r[3];
    }
    #pragma unroll
    for (int mt = 0; mt < 4; mt++)
        #pragma unroll
        for (int nt = 0; nt < 4; nt++){
            mma16816(acc[mt][nt], ah[mt], bh[nt]);
            mma16816(acc[mt][nt], ah[mt], bl[nt]);
            mma16816(acc[mt][nt], al[mt], bh[nt]);
        }
}

// ---------------- GEMM A[·,512] x W^T -> C[128,128] tiles (4-stage cp.async) ----------------
__global__ void __launch_bounds__(256) mm_k(
    const __nv_bfloat16* __restrict__ Ah0, const __nv_bfloat16* __restrict__ Al0,
    const __nv_bfloat16* __restrict__ Ah1, const __nv_bfloat16* __restrict__ Al1,
    int wbase, float* C0, float* C1, float* C2,
    __nv_bfloat16* Hh, __nv_bfloat16* Hl, float hscale, int hz0, int guard)
{
    extern __shared__ char smem[];
    int z = blockIdx.z;
    const __nv_bfloat16* Ah = (z==1) ? Ah1 : Ah0;
    const __nv_bfloat16* Al = (z==1) ? Al1 : Al0;
    const __nv_bfloat16* Bh = g_wth + (size_t)(wbase+z)*HD*HD;
    const __nv_bfloat16* Bl = g_wtl + (size_t)(wbase+z)*HD*HD;
    float* C = (z==0) ? C0 : ((z==1) ? C1 : C2);
    int tbm = blockIdx.y*128, tbn = blockIdx.x*128;
    if (guard && tbm >= g_nvalid) return;
    unsigned s0 = smem_u32(smem);
    int tid = threadIdx.x, lane = tid & 31, warp = tid >> 5;
    int wm = warp & 1, wn = warp >> 1;
    int row = tid >> 1, half = tid & 1;
    size_t aoff = (size_t)(tbm+row)*HD + half*8;
    size_t boff = (size_t)(tbn+row)*HD + half*8;
    unsigned sdst = (row*KSTR + half*8)*2;

    float acc[4][4][4];
    #pragma unroll
    for (int i = 0; i < 4; i++)
        #pragma unroll
        for (int j2 = 0; j2 < 4; j2++){ acc[i][j2][0]=0.f; acc[i][j2][1]=0.f; acc[i][j2][2]=0.f; acc[i][j2][3]=0.f; }

    #pragma unroll
    for (int s = 0; s < 3; s++){
        unsigned b = s0 + s*STG + sdst;
        cpa16(b,       &Ah[aoff + s*16]);
        cpa16(b+ARR,   &Al[aoff + s*16]);
        cpa16(b+2*ARR, &Bh[boff + s*16]);
        cpa16(b+3*ARR, &Bl[boff + s*16]);
        CP_COMMIT();
    }
    for (int it = 0; it < 32; it++){
        CP_WAIT2();
        __syncthreads();
        mma_stage(s0 + (it&3)*STG, wm, wn, lane, acc);
        if (it + 3 < 32){
            unsigned b = s0 + ((it+3)&3)*STG + sdst;
            cpa16(b,       &Ah[aoff + (it+3)*16]);
            cpa16(b+ARR,   &Al[aoff + (it+3)*16]);
            cpa16(b+2*ARR, &Bh[boff + (it+3)*16]);
            cpa16(b+3*ARR, &Bl[boff + (it+3)*16]);
        }
        CP_COMMIT();
    }
    #pragma unroll
    for (int mt = 0; mt < 4; mt++){
        int m0 = tbm + wm*64 + mt*16 + (lane>>2);
        #pragma unroll
        for (int nt = 0; nt < 4; nt++){
            int n = tbn + wn*32 + nt*8 + (lane&3)*2;
            float* c = acc[mt][nt];
            size_t i0 = (size_t)m0*HD + n, i1 = (size_t)(m0+8)*HD + n;
            *(float2*)&C[i0] = make_float2(c[0], c[1]);
            *(float2*)&C[i1] = make_float2(c[2], c[3]);
            if (hz0 && z == 0){
                float s0v = c[0]*hscale, s1v = c[1]*hscale, s2v = c[2]*hscale, s3v = c[3]*hscale;
                __nv_bfloat16 h0 = __float2bfloat16(s0v), h1 = __float2bfloat16(s1v);
                __nv_bfloat16 h2 = __float2bfloat16(s2v), h3 = __float2bfloat16(s3v);
                *(__nv_bfloat162*)&Hh[i0] = __nv_bfloat162(h0, h1);
                *(__nv_bfloat162*)&Hh[i1] = __nv_bfloat162(h2, h3);
                *(__nv_bfloat162*)&Hl[i0] = __nv_bfloat162(
                    __float2bfloat16(s0v-__bfloat162float(h0)), __float2bfloat16(s1v-__bfloat162float(h1)));
                *(__nv_bfloat162*)&Hl[i1] = __nv_bfloat162(
                    __float2bfloat16(s2v-__bfloat162float(h2)), __float2bfloat16(s3v-__bfloat162float(h3)));
            }
        }
    }
}

// ---------------- fused flash compressed attention ----------------
#define QPL  18432
#define KVPL 9216
#define KVST 18432
#define FASM (36864 + 36864 + 36864)

__global__ void __launch_bounds__(256) fa_k(){
    extern __shared__ char smem[];
    unsigned s0 = smem_u32(smem);
    unsigned Kb = s0 + 36864, Vb = s0 + 73728;
    int h = blockIdx.y, nt = blockIdx.x*128;
    int nv = g_nvalid;
    int njt = (nv + 63) >> 6;
    int tid = threadIdx.x, lane = tid & 31, w = tid >> 5;
    int tg = lane & 3, gp = lane >> 2;
    int t7 = lane & 7, t8 = lane >> 3;

    #pragma unroll
    for (int q = 0; q < 8; q++){
        int jb = tid + 256*q, pl = jb >> 10, rem = jb & 1023, row = rem >> 3, c8 = rem & 7;
        const __nv_bfloat16* src = pl ? g_ql : g_qh;
        float4 v = *(const float4*)&src[(size_t)(nt+row)*HD + h*DH + c8*8];
        sts128(s0 + pl*QPL + (row*72 + c8*8)*2, v);
    }
    __syncthreads();
    unsigned aqh[4][4], aql[4][4];
    #pragma unroll
    for (int kc = 0; kc < 4; kc++){
        unsigned off = ((w*16 + (t8&1)*8 + t7)*72 + kc*16 + (t8>>1)*8)*2;
        ldsm4(aqh[kc], s0 + off);
        ldsm4(aql[kc], s0 + QPL + off);
    }

    float m0 = -3.0e38f, m1 = -3.0e38f, l0 = 0.f, l1 = 0.f;
    float co[8][4];
    #pragma unroll
    for (int i = 0; i < 8; i++){ co[i][0]=0.f; co[i][1]=0.f; co[i][2]=0.f; co[i][3]=0.f; }

    float4 kr[4], vr[4];
    #pragma unroll
    for (int q = 0; q < 4; q++){
        int jb = tid + 256*q, pl = jb >> 9, rem = jb & 511, row = rem >> 3, c8 = rem & 7;
        const __nv_bfloat16* ks = pl ? g_ckl : g_ckh;
        kr[q] = *(const float4*)&ks[(size_t)row*HD + h*DH + c8*8];
        const __nv_bfloat16* vs = pl ? g_cvtl : g_cvth;
        vr[q] = *(const float4*)&vs[(size_t)(h*DH+row)*MB + c8*8];
    }
    #pragma unroll
    for (int q = 0; q < 4; q++){
        int jb = tid + 256*q, pl = jb >> 9, rem = jb & 511, row = rem >> 3, c8 = rem & 7;
        unsigned off = pl*KVPL + (row*72 + c8*8)*2;
        sts128(Kb + off, kr[q]);
        sts128(Vb + off, vr[q]);
    }
    __syncthreads();

    for (int t = 0; t < njt; t++){
        if (t+1 < njt){
            int j0 = (t+1)*64;
            #pragma unroll
            for (int q = 0; q < 4; q++){
                int jb = tid + 256*q, pl = jb >> 9, rem = jb & 511, row = rem >> 3, c8 = rem & 7;
                const __nv_bfloat16* ks = pl ? g_ckl : g_ckh;
                kr[q] = *(const float4*)&ks[(size_t)(j0+row)*HD + h*DH + c8*8];
                const __nv_bfloat16* vs = pl ? g_cvtl : g_cvth;
                vr[q] = *(const float4*)&vs[(size_t)(h*DH+row)*MB + j0 + c8*8];
            }
        }
        int st = t & 1;
        float cs[8][4];
        #pragma unroll
        for (int i = 0; i < 8; i++){ cs[i][0]=0.f; cs[i][1]=0.f; cs[i][2]=0.f; cs[i][3]=0.f; }
        #pragma unroll
        for (int kc = 0; kc < 4; kc++){
            unsigned bh[8][2], bl[8][2];
            #pragma unroll
            for (int p = 0; p < 4; p++){
                unsigned off = Kb + st*KVST + ((p*16 + (t8>>1)*8 + t7)*72 + kc*16 + (t8&1)*8)*2;
                unsigned r[4];
                ldsm4(r, off);
                bh[2*p][0]=r[0]; bh[2*p][1]=r[1]; bh[2*p+1][0]=r[2]; bh[2*p+1][1]=r[3];
                ldsm4(r, off + KVPL);
                bl[2*p][0]=r[0]; bl[2*p][1]=r[1]; bl[2*p+1][0]=r[2]; bl[2*p+1][1]=r[3];
            }
            #pragma unroll
            for (int n8 = 0; n8 < 8; n8++){
                mma16816(cs[n8], aqh[kc], bh[n8]);
                mma16816(cs[n8], aqh[kc], bl[n8]);
                mma16816(cs[n8], aql[kc], bh[n8]);
            }
        }
        int jb0 = t*64 + tg*2;
        float tm0 = -3.0e38f, tm1 = -3.0e38f;
        #pragma unroll
        for (int n8 = 0; n8 < 8; n8++){
            int j = jb0 + n8*8;
            if (j   >= nv){ cs[n8][0] = -3.0e38f; cs[n8][2] = -3.0e38f; }
            if (j+1 >= nv){ cs[n8][1] = -3.0e38f; cs[n8][3] = -3.0e38f; }
            tm0 = fmaxf(tm0, fmaxf(cs[n8][0], cs[n8][1]));
            tm1 = fmaxf(tm1, fmaxf(cs[n8][2], cs[n8][3]));
        }
        tm0 = fmaxf(tm0, __shfl_xor_sync(0xffffffffu, tm0, 1));
        tm0 = fmaxf(tm0, __shfl_xor_sync(0xffffffffu, tm0, 2));
        tm1 = fmaxf(tm1, __shfl_xor_sync(0xffffffffu, tm1, 1));
        tm1 = fmaxf(tm1, __shfl_xor_sync(0xffffffffu, tm1, 2));
        float nm0 = fmaxf(m0, tm0), nm1 = fmaxf(m1, tm1);
        float f0 = fexp(m0 - nm0), f1 = fexp(m1 - nm1);
        m0 = nm0; m1 = nm1;
        l0 *= f0; l1 *= f1;
        #pragma unroll
        for (int d8 = 0; d8 < 8; d8++){
            co[d8][0] *= f0; co[d8][1] *= f0; co[d8][2] *= f1; co[d8][3] *= f1;
        }
        unsigned pah[4][4], pal[4][4];
        #pragma unroll
        for (int kc = 0; kc < 4; kc++){
            float e00 = fexp(cs[2*kc][0] - m0),   e01 = fexp(cs[2*kc][1] - m0);
            float e02 = fexp(cs[2*kc][2] - m1),   e03 = fexp(cs[2*kc][3] - m1);
            float e10 = fexp(cs[2*kc+1][0] - m0), e11 = fexp(cs[2*kc+1][1] - m0);
            float e12 = fexp(cs[2*kc+1][2] - m1), e13 = fexp(cs[2*kc+1][3] - m1);
            l0 += e00 + e01 + e10 + e11;
            l1 += e02 + e03 + e12 + e13;
            __nv_bfloat16 h00=__float2bfloat16(e00), h01=__float2bfloat16(e01);
            __nv_bfloat16 h02=__float2bfloat16(e02), h03=__float2bfloat16(e03);
            __nv_bfloat16 h10=__float2bfloat16(e10), h11=__float2bfloat16(e11);
            __nv_bfloat16 h12=__float2bfloat16(e12), h13=__float2bfloat16(e13);
            pah[kc][0] = pack2(h00, h01);
            pah[kc][1] = pack2(h02, h03);
            pah[kc][2] = pack2(h10, h11);
            pah[kc][3] = pack2(h12, h13);
            pal[kc][0] = pack2(__float2bfloat16(e00-__bfloat162float(h00)), __float2bfloat16(e01-__bfloat162float(h01)));
            pal[kc][1] = pack2(__float2bfloat16(e02-__bfloat162float(h02)), __float2bfloat16(e03-__bfloat162float(h03)));
            pal[kc][2] = pack2(__float2bfloat16(e10-__bfloat162float(h10)), __float2bfloat16(e11-__bfloat162float(h11)));
            pal[kc][3] = pack2(__float2bfloat16(e12-__bfloat162float(h12)), __float2bfloat16(e13-__bfloat162float(h13)));
        }
        #pragma unroll
        for (int kc = 0; kc < 4; kc++){
            unsigned bh[8][2], bl[8][2];
            #pragma unroll
            for (int p = 0; p < 4; p++){
                unsigned off = Vb + st*KVST + ((p*16 + (t8>>1)*8 + t7)*72 + kc*16 + (t8&1)*8)*2;
                unsigned r[4];
                ldsm4(r, off);
                bh[2*p][0]=r[0]; bh[2*p][1]=r[1]; bh[2*p+1][0]=r[2]; bh[2*p+1][1]=r[3];
                ldsm4(r, off + KVPL);
                bl[2*p][0]=r[0]; bl[2*p][1]=r[1]; bl[2*p+1][0]=r[2]; bl[2*p+1][1]=r[3];
            }
            #pragma unroll
            for (int d8 = 0; d8 < 8; d8++){
                mma16816(co[d8], pah[kc], bh[d8]);
                mma16816(co[d8], pah[kc], bl[d8]);
                mma16816(co[d8], pal[kc], bh[d8]);
            }
        }
        if (t+1 < njt){
            int nst = (t+1) & 1;
            #pragma unroll
            for (int q = 0; q < 4; q++){
                int jb = tid + 256*q, pl = jb >> 9, rem = jb & 511, row = rem >> 3, c8 = rem & 7;
                unsigned off = pl*KVPL + (row*72 + c8*8)*2;
                sts128(Kb + nst*KVST + off, kr[q]);
                sts128(Vb + nst*KVST + off, vr[q]);
            }
            __syncthreads();
        }
    }
    l0 += __shfl_xor_sync(0xffffffffu, l0, 1);
    l0 += __shfl_xor_sync(0xffffffffu, l0, 2);
    l1 += __shfl_xor_sync(0xffffffffu, l1, 1);
    l1 += __shfl_xor_sync(0xffffffffu, l1, 2);
    float iv0 = 1.0f / l0, iv1 = 1.0f / l1;
    int row0 = nt + w*16 + gp;
    if (tg == 0){
        g_invl[h*NTOK + row0]     = iv0;
        g_invl[h*NTOK + row0 + 8] = iv1;
        g_rowm[h*NTOK + row0]     = m0;
        g_rowm[h*NTOK + row0 + 8] = m1;
    }
    #pragma unroll
    for (int d8 = 0; d8 < 8; d8++){
        int col = h*DH + d8*8 + tg*2;
        *(float2*)&g_outc[(size_t)row0*HD + col]     = make_float2(co[d8][0]*iv0, co[d8][1]*iv0);
        *(float2*)&g_outc[(size_t)(row0+8)*HD + col] = make_float2(co[d8][2]*iv1, co[d8][3]*iv1);
    }
}

// ---------------- P8: recompute S per head (double-buffered via cp.async) ----------------
#define P8ST 73728
#define P8SM (2*P8ST)

__device__ __forceinline__ void p8_issue(unsigned base, int ntb, int jt, int h, int tid){
    #pragma unroll
    for (int q = 0; q < 8; q++){
        int jb = tid + 256*q, pl = jb >> 10, rem = jb & 1023, row = rem >> 3, c8 = rem & 7;
        const __nv_bfloat16* qs = pl ? g_ql : g_qh;
        const __nv_bfloat16* ks = pl ? g_ckl : g_ckh;
        unsigned off = pl*QPL + (row*72 + c8*8)*2;
        cpa16(base + off,         &qs[(size_t)(ntb+row)*HD + h*DH + c8*8]);
        cpa16(base + 36864 + off, &ks[(size_t)(jt+row)*HD + h*DH + c8*8]);
    }
}

__global__ void __launch_bounds__(256) p8_k(){
    extern __shared__ char smem[];
    unsigned s0 = smem_u32(smem);
    int ntb = blockIdx.x*128, jt = blockIdx.y*128;
    int nv = g_nvalid;
    if (jt >= nv) return;
    int tid = threadIdx.x, lane = tid & 31, w = tid >> 5;
    int tg = lane & 3, gp = lane >> 2;
    int t7 = lane & 7, t8 = lane >> 3;
    int row0 = ntb + w*16 + gp;

    float acc[16][4];
    #pragma unroll
    for (int i = 0; i < 16; i++){ acc[i][0]=0.f; acc[i][1]=0.f; acc[i][2]=0.f; acc[i][3]=0.f; }

    p8_issue(s0, ntb, jt, 0, tid); CP_COMMIT();
    for (int h = 0; h < NH; h++){
        if (h < 7){ p8_issue(s0 + ((h+1)&1)*P8ST, ntb, jt, h+1, tid); CP_COMMIT(); }
        if (h < 7) CP_WAIT1(); else CP_WAIT0();
        __syncthreads();
        unsigned qb = s0 + (h&1)*P8ST, kb = qb + 36864;
        unsigned aqh[4][4], aql[4][4];
        #pragma unroll
        for (int kc = 0; kc < 4; kc++){
            unsigned off = ((w*16 + (t8&1)*8 + t7)*72 + kc*16 + (t8>>1)*8)*2;
            ldsm4(aqh[kc], qb + off);
            ldsm4(aql[kc], qb + QPL + off);
        }
        float cs[16][4];
        #pragma unroll
        for (int i = 0; i < 16; i++){ cs[i][0]=0.f; cs[i][1]=0.f; cs[i][2]=0.f; cs[i][3]=0.f; }
        #pragma unroll
        for (int kc = 0; kc < 4; kc++){
            unsigned bh[16][2], bl[16][2];
            #pragma unroll
            for (int p = 0; p < 8; p++){
                unsigned off = kb + ((p*16 + (t8>>1)*8 + t7)*72 + kc*16 + (t8&1)*8)*2;
                unsigned r[4];
                ldsm4(r, off);
                bh[2*p][0]=r[0]; bh[2*p][1]=r[1]; bh[2*p+1][0]=r[2]; bh[2*p+1][1]=r[3];
                ldsm4(r, off + QPL);
                bl[2*p][0]=r[0]; bl[2*p][1]=r[1]; bl[2*p+1][0]=r[2]; bl[2*p+1][1]=r[3];
            }
            #pragma unroll
            for (int n8 = 0; n8 < 16; n8++){
                mma16816(cs[n8], aqh[kc], bh[n8]);
                mma16816(cs[n8], aqh[kc], bl[n8]);
                mma16816(cs[n8], aql[kc], bh[n8]);
            }
        }
        float m0 = g_rowm[h*NTOK + row0],     iv0 = g_invl[h*NTOK + row0];
        float m1 = g_rowm[h*NTOK + row0 + 8], iv1 = g_invl[h*NTOK + row0 + 8];
        #pragma unroll
        for (int n8 = 0; n8 < 16; n8++){
            int j = jt + n8*8 + tg*2;
            if (j < nv){
                acc[n8][0] += fexp(cs[n8][0] - m0) * iv0;
                acc[n8][2] += fexp(cs[n8][2] - m1) * iv1;
            }
            if (j+1 < nv){
                acc[n8][1] += fexp(cs[n8][1] - m0) * iv0;
                acc[n8][3] += fexp(cs[n8][3] - m1) * iv1;
            }
        }
        __syncthreads();
    }
    #pragma unroll
    for (int n8 = 0; n8 < 16; n8++){
        int j = jt + n8*8 + tg*2;
        *(float2*)&g_P8[(size_t)row0*MB + j]     = make_float2(acc[n8][0], acc[n8][1]);
        *(float2*)&g_P8[(size_t)(row0+8)*MB + j] = make_float2(acc[n8][2], acc[n8][3]);
    }
}

// ---------------- merged top-8 + selection/window attention ----------------
__global__ void tsp_k(){
    int n = blockIdx.x, tid = threadIdx.x;
    int lane = tid & 31, w = tid >> 5;
    __shared__ float ss[SBN];
    __shared__ float wv[16];
    __shared__ int   wi[16];
    __shared__ int   t8s[8];
    float v = 0.f;
    int o0 = g_soff[tid], o1 = g_soff[tid+1];
    for (int i = o0; i < o1; i++) v += g_P8[(size_t)n*MB + g_slist[i]];
    ss[tid] = v;
    __syncthreads();
    for (int r = 0; r < 8; r++){
        float mv = ss[tid]; int mi = tid;
        #pragma unroll
        for (int o = 16; o; o >>= 1){
            float ov = __shfl_xor_sync(0xffffffffu, mv, o);
            int   oi = __shfl_xor_sync(0xffffffffu, mi, o);
            if (ov > mv || (ov == mv && oi < mi)){ mv = ov; mi = oi; }
        }
        if (lane == 0){ wv[w] = mv; wi[w] = mi; }
        __syncthreads();
        if (tid < 16){
            float m2 = wv[tid]; int i2 = wi[tid];
            #pragma unroll
            for (int o = 8; o; o >>= 1){
                float ov = __shfl_xor_sync(0x0000ffffu, m2, o);
                int   oi = __shfl_xor_sync(0x0000ffffu, i2, o);
                if (ov > m2 || (ov == m2 && oi < i2)){ m2 = ov; i2 = oi; }
            }
            if (tid == 0){ t8s[r] = i2; ss[i2] = -1e30f; }
        }
        __syncthreads();
    }
    // phase 2: warps 0-7 selection (h=w), warps 8-15 window (h=w-8)
    int mode = w >> 3, h = w & 7;
    const float* qr = &g_q[n*HD + h*DH];
    float q0 = qr[lane], q1 = qr[lane + 32];
    float m = -1e30f, l = 0.f, a0 = 0.f, a1 = 0.f;
    int nb = (mode == 0) ? 8 : 1;
    for (int kk = 0; kk < nb; kk++){
        int b, o, e;
        if (mode == 0){ b = t8s[kk];  o = g_sboff[b]; e = g_sboff[b+1]; }
        else          { b = g_wid[n]; o = g_woff[b];  e = g_woff[b+1]; }
        for (int i = o; i < e; i++){
            int t = (mode == 0) ? g_sbperm[i] : g_wperm[i];
            const float* kr = &g_kf[t*HD + h*DH];
            float s = q0*kr[lane] + q1*kr[lane + 32];
            #pragma unroll
            for (int of = 16; of; of >>= 1) s += __shfl_xor_sync(0xffffffffu, s, of);
            s *= 0.125f;
            float mn = fmaxf(m, s);
            float c = fexp(m - mn), ww = fexp(s - mn);
            const float* vr = &g_vf[t*HD + h*DH];
            l  = l*c  + ww;
            a0 = a0*c + ww*vr[lane];
            a1 = a1*c + ww*vr[lane + 32];
            m = mn;
        }
    }
    float* outp = mode ? g_outw : g_outs;
    outp[n*HD + h*DH + lane]      = a0 / l;
    outp[n*HD + h*DH + lane + 32] = a1 / l;
}

// ---------------- gated fuse -> split bf16 ----------------
__global__ void fuse_k(){
    int i = blockIdx.x*256 + threadIdx.x;
    int n = i >> 9;
    float g0 = g_gate[n*3+0], g1 = g_gate[n*3+1], g2 = g_gate[n*3+2];
    float v = g0*g_outc[i] + g1*g_outs[i] + g2*g_outw[i];
    __nv_bfloat16 hb = __float2bfloat16(v);
    g_fh[i] = hb;
    g_fl[i] = __float2bfloat16(v - __bfloat162float(hb));
}

// ---------------- launch ----------------
extern "C" void kernel_launch(void* const* d_in, const int* in_sizes, int n_in,
                              void* d_out, int out_size){
    const float* feats  = (const float*)d_in[0];
    const int*   coords = (const int*)  d_in[1];
    const float* Wq  = (const float*)d_in[2];
    const float* Wk  = (const float*)d_in[3];
    const float* Wv  = (const float*)d_in[4];
    const float* Wo  = (const float*)d_in[5];
    const float* Wck = (const float*)d_in[6];
    const float* Wcv = (const float*)d_in[7];
    const float* pe  = (const float*)d_in[8];
    const float* Wg  = (const float*)d_in[9];
    float* out = (float*)d_out;

    float *gq, *gkf, *gvf, *gck, *gcv;
    __nv_bfloat16 *fh, *fl, *qh, *ql, *kah, *kal, *vah, *val, *ckh, *ckl;
    cudaGetSymbolAddress((void**)&gq,  g_q);
    cudaGetSymbolAddress((void**)&gkf, g_kf);
    cudaGetSymbolAddress((void**)&gvf, g_vf);
    cudaGetSymbolAddress((void**)&gck, g_ck);
    cudaGetSymbolAddress((void**)&gcv, g_cv);
    cudaGetSymbolAddress((void**)&fh,  g_fh);
    cudaGetSymbolAddress((void**)&fl,  g_fl);
    cudaGetSymbolAddress((void**)&qh,  g_qh);
    cudaGetSymbolAddress((void**)&ql,  g_ql);
    cudaGetSymbolAddress((void**)&kah, g_kah);
    cudaGetSymbolAddress((void**)&kal, g_kal);
    cudaGetSymbolAddress((void**)&vah, g_vah);
    cudaGetSymbolAddress((void**)&val, g_val);
    cudaGetSymbolAddress((void**)&ckh, g_ckh);
    cudaGetSymbolAddress((void**)&ckl, g_ckl);

    cudaFuncSetAttribute(mm_k, cudaFuncAttributeMaxDynamicSharedMemorySize, MMSM);
    cudaFuncSetAttribute(fa_k, cudaFuncAttributeMaxDynamicSharedMemorySize, FASM);
    cudaFuncSetAttribute(p8_k, cudaFuncAttributeMaxDynamicSharedMemorySize, P8SM);

    zero_k<<<64, 256>>>();
    prep_k<<<8, 256>>>(coords);
    init2_k<<<6656, 256>>>(feats, Wq, Wk, Wv, Wck, Wcv, Wo, Wg);

    mm_k<<<dim3(4, NTOK/128, 3), 256, MMSM>>>(fh, fl, fh, fl, 0, gq, gkf, gvf, qh, ql, 0.125f, 1, 0);

    scan1_k<<<1, 128>>>();
    permcnt_k<<<dim3(8, 8), 256>>>();
    permscat_k<<<8, 256>>>();
    avg_k<<<MB, 256>>>(pe);

    mm_k<<<dim3(4, MB/128, 2), 256, MMSM>>>(kah, kal, vah, val, 3, gck, gcv, gcv, ckh, ckl, 1.0f, 1, 1);
    cvt_k<<<dim3(MB/32, HD/32), 256>>>();

    scan2_k<<<1, 32>>>();
    scnt_k<<<dim3(8, 8), 256>>>();
    sscat_k<<<8, 256>>>();

    fa_k<<<dim3(NTOK/128, NH), 256, FASM>>>();
    p8_k<<<dim3(NTOK/128, 13), 256, P8SM>>>();
    tsp_k<<<NTOK, 512>>>();
    fuse_k<<<NTOK*HD/256, 256>>>();

    mm_k<<<dim3(4, NTOK/128, 1), 256, MMSM>>>(fh, fl, fh, fl, 5, out, out, out, qh, ql, 1.0f, 0, 0);
}

// round 13
// speedup vs baseline: 1.0246x; 1.0246x over previous
#include <cuda_runtime.h>
#include <cuda_bf16.h>

#define NTOK 2048
#define HD   512
#define NH   8
#define DH   64
#define MB   4096
#define SBN  512
#define NWID 729

// ---------------- scratch ----------------
__device__ float g_q[NTOK*HD], g_kf[NTOK*HD], g_vf[NTOK*HD];
__device__ float g_ck[MB*HD], g_cv[MB*HD];
__device__ float g_P8[(size_t)NTOK*MB];
__device__ float g_invl[NH*NTOK];
__device__ float g_rowm[NH*NTOK];
__device__ float g_outc[NTOK*HD], g_outs[NTOK*HD], g_outw[NTOK*HD];
__device__ float g_gate[NTOK*3];
__device__ int g_cnt[MB], g_boff[MB+1], g_bperm[NTOK], g_bid[NTOK];
__device__ int g_sbcnt[SBN], g_sboff[SBN+1], g_sbperm[NTOK], g_sbid[NTOK];
__device__ int g_wcnt[NWID], g_woff[NWID+1], g_wperm[NTOK], g_wid[NTOK];
__device__ int g_scount[SBN], g_soff[SBN+1], g_slist[MB], g_sidc[MB];
__device__ int g_vlist[MB], g_nvalid;
__device__ int g_pei[NTOK], g_packed[NTOK];
__device__ int g_r1[NTOK], g_r2[NTOK], g_r3[NTOK], g_rs[MB];
// split-bf16 operands
__device__ __nv_bfloat16 g_wth[6*HD*HD], g_wtl[6*HD*HD];
__device__ __nv_bfloat16 g_fh[NTOK*HD], g_fl[NTOK*HD];
__device__ __nv_bfloat16 g_qh[NTOK*HD], g_ql[NTOK*HD];   // pre-scaled by 0.125
__device__ __nv_bfloat16 g_kah[MB*HD], g_kal[MB*HD], g_vah[MB*HD], g_val[MB*HD];
__device__ __nv_bfloat16 g_ckh[MB*HD], g_ckl[MB*HD];
__device__ __nv_bfloat16 g_cvth[NH*DH*MB], g_cvtl[NH*DH*MB];

// ---------------- helpers ----------------
__device__ __forceinline__ unsigned smem_u32(const void* p){
    unsigned a;
    asm("{ .reg .u64 t; cvta.to.shared.u64 t, %1; cvt.u32.u64 %0, t; }" : "=r"(a) : "l"(p));
    return a;
}
__device__ __forceinline__ void sts128(unsigned a, float4 v){
    asm volatile("st.shared.v4.b32 [%0], {%1,%2,%3,%4};" :: "r"(a),
        "r"(__float_as_uint(v.x)), "r"(__float_as_uint(v.y)),
        "r"(__float_as_uint(v.z)), "r"(__float_as_uint(v.w)) : "memory");
}
__device__ __forceinline__ void ldsm4(unsigned* r, unsigned addr){
    asm volatile("ldmatrix.sync.aligned.m8n8.x4.shared.b16 {%0,%1,%2,%3}, [%4];"
        : "=r"(r[0]), "=r"(r[1]), "=r"(r[2]), "=r"(r[3]) : "r"(addr));
}
__device__ __forceinline__ void mma16816(float* c, const unsigned* a, const unsigned* b){
    asm volatile("mma.sync.aligned.m16n8k16.row.col.f32.bf16.bf16.f32 "
        "{%0,%1,%2,%3}, {%4,%5,%6,%7}, {%8,%9}, {%0,%1,%2,%3};"
        : "+f"(c[0]), "+f"(c[1]), "+f"(c[2]), "+f"(c[3])
        : "r"(a[0]), "r"(a[1]), "r"(a[2]), "r"(a[3]), "r"(b[0]), "r"(b[1]));
}
__device__ __forceinline__ float fexp(float x){
    x = fminf(fmaxf(x, -87.0f), 88.0f);
    float y = x * 1.4426950408889634f;
    float z = y + 12582912.0f;
    int ki = __float_as_int(z) - 0x4B400000;
    float f = y - (z - 12582912.0f);
    float p = 1.5403530393381609e-4f;
    p = fmaf(p, f, 1.3333558146428443e-3f);
    p = fmaf(p, f, 9.6181291076284772e-3f);
    p = fmaf(p, f, 5.5504108664821580e-2f);
    p = fmaf(p, f, 2.4022650695910071e-1f);
    p = fmaf(p, f, 6.9314718055994531e-1f);
    p = fmaf(p, f, 1.0f);
    return __int_as_float((ki + 127) << 23) * p;
}
__device__ __forceinline__ unsigned pack2(__nv_bfloat16 a, __nv_bfloat16 b){
    return ((unsigned)__bfloat16_as_ushort(b) << 16) | __bfloat16_as_ushort(a);
}

// ---------------- setup ----------------
__global__ void zero_k(){
    int i = blockIdx.x*256 + threadIdx.x;
    if (i < MB){ g_cnt[i] = 0; g_rs[i] = 0; }
    if (i < SBN){ g_sbcnt[i] = 0; g_scount[i] = 0; }
    if (i < NWID) g_wcnt[i] = 0;
    if (i < NTOK){ g_r1[i] = 0; g_r2[i] = 0; g_r3[i] = 0; }
}
__global__ void prep_k(const int* __restrict__ coords){
    int t = blockIdx.x*256 + threadIdx.x;
    if (t >= NTOK) return;
    int cf = coords[t];
    int x = cf >> 12, y = (cf >> 6) & 63, z = cf & 63;
    int bid = ((x>>2)<<8) | ((y>>2)<<4) | (z>>2);
    g_bid[t] = bid; atomicAdd(&g_cnt[bid], 1);
    int sb = ((x>>3)<<6) | ((y>>3)<<3) | (z>>3);
    g_sbid[t] = sb; atomicAdd(&g_sbcnt[sb], 1);
    int wd = (((x+4)>>3)*9 + ((y+4)>>3))*9 + ((z+4)>>3);
    g_wid[t] = wd; atomicAdd(&g_wcnt[wd], 1);
    g_pei[t] = (((x&3)*4 + (y&3))*4 + (z&3)) * HD;
    g_packed[t] = bid | (sb << 12) | (wd << 21);
}
// merged: convW (blocks 0..1535) + convA (1536..5631) + gate (5632..6655)
__global__ void init2_k(const float* __restrict__ feats,
    const float* W0, const float* W1, const float* W2,
    const float* W3, const float* W4, const float* W5,
    const float* __restrict__ Wg){
    __shared__ float t[32][33];
    int bid = blockIdx.x, tid = threadIdx.x;
    if (bid < 1536){
        int z = bid >> 8, rem = bid & 255;
        int bn = (rem & 15)*32, bk = (rem >> 4)*32;
        const float* W = z==0?W0 : z==1?W1 : z==2?W2 : z==3?W3 : z==4?W4 : W5;
        __nv_bfloat16* h = g_wth + (size_t)z*HD*HD;
        __nv_bfloat16* l = g_wtl + (size_t)z*HD*HD;
        int tx = tid & 31, ty = tid >> 5;
        for (int r = ty; r < 32; r += 8) t[r][tx] = W[(size_t)(bk+r)*HD + bn + tx];
        __syncthreads();
        for (int r = ty; r < 32; r += 8){
            float x = t[tx][r];
            __nv_bfloat16 hb = __float2bfloat16(x);
            h[(size_t)(bn+r)*HD + bk + tx] = hb;
            l[(size_t)(bn+r)*HD + bk + tx] = __float2bfloat16(x - __bfloat162float(hb));
        }
    } else if (bid < 5632){
        int i = (bid - 1536)*256 + tid;
        float x = feats[i];
        __nv_bfloat16 hb = __float2bfloat16(x);
        g_fh[i] = hb; g_fl[i] = __float2bfloat16(x - __bfloat162float(hb));
    } else {
        int n = (bid - 5632)*2 + (tid >> 7);
        int sub = tid & 127, w = sub >> 5, lane = sub & 31;
        if (w < 3){
            float s = 0.f;
            for (int i = lane; i < HD; i += 32) s += feats[n*HD + i] * Wg[i*3 + w];
            #pragma unroll
            for (int o = 16; o; o >>= 1) s += __shfl_xor_sync(0xffffffffu, s, o);
            if (lane == 0) g_gate[n*3 + w] = 1.0f / (1.0f + fexp(-s));
        }
    }
}
__device__ __forceinline__ void warp_exscan(const int* cnt, int* off, int len){
    int lane = threadIdx.x & 31;
    int run = 0;
    for (int base = 0; base < len; base += 32){
        int raw = (base+lane < len) ? cnt[base+lane] : 0;
        int v = raw;
        #pragma unroll
        for (int o = 1; o < 32; o <<= 1){ int t = __shfl_up_sync(0xffffffffu, v, o); if (lane >= o) v += t; }
        if (base+lane < len) off[base+lane] = run + v - raw;
        run += __shfl_sync(0xffffffffu, v, 31);
    }
    if (lane == 0) off[len] = run;
}
__global__ void scan1_k(){
    int w = threadIdx.x >> 5;
    if (w == 0) warp_exscan(g_cnt, g_boff, MB);
    else if (w == 1) warp_exscan(g_sbcnt, g_sboff, SBN);
    else if (w == 2) warp_exscan(g_wcnt, g_woff, NWID);
    else {
        int lane = threadIdx.x & 31;
        int run = 0;
        for (int base = 0; base < MB; base += 32){
            int valid = g_cnt[base+lane] > 0 ? 1 : 0;
            int v = valid;
            #pragma unroll
            for (int o = 1; o < 32; o <<= 1){ int t = __shfl_up_sync(0xffffffffu, v, o); if (lane >= o) v += t; }
            if (valid) g_vlist[run + v - 1] = base + lane;
            run += __shfl_sync(0xffffffffu, v, 31);
        }
        if (lane == 0) g_nvalid = run;
    }
}
__global__ void scan2_k(){ warp_exscan(g_scount, g_soff, SBN); }

__global__ void permcnt_k(){
    int bt = blockIdx.x, bu = blockIdx.y;
    if (bu > bt) return;
    __shared__ int sp[256];
    int tid = threadIdx.x;
    int t = bt*256 + tid;
    sp[tid] = g_packed[bu*256 + tid];
    __syncthreads();
    int my = g_packed[t];
    int lim = (bu < bt) ? 256 : tid;
    int r1 = 0, r2 = 0, r3 = 0;
    for (int u = 0; u < lim; u++){
        int p = sp[u] ^ my;
        r3 += ((p & 0x00000FFF) == 0);
        r1 += ((p & 0x001FF000) == 0);
        r2 += ((p & 0x7FE00000) == 0);
    }
    if (r1) atomicAdd(&g_r1[t], r1);
    if (r2) atomicAdd(&g_r2[t], r2);
    if (r3) atomicAdd(&g_r3[t], r3);
}
__global__ void permscat_k(){
    int t = blockIdx.x*256 + threadIdx.x;
    if (t >= NTOK) return;
    int my = g_packed[t];
    int bd = my & 0xFFF, sb = (my >> 12) & 0x1FF, wd = (my >> 21) & 0x3FF;
    g_sbperm[g_sboff[sb] + g_r1[t]] = t;
    g_wperm [g_woff[wd]  + g_r2[t]] = t;
    g_bperm [g_boff[bd]  + g_r3[t]] = t;
}
__global__ void scnt_k(){
    int bj = blockIdx.x, bu = blockIdx.y;
    if (bu > bj) return;
    __shared__ int sp[256];
    int tid = threadIdx.x;
    int nv = g_nvalid;
    int ju = bu*256 + tid;
    sp[tid] = (ju < nv) ? g_sidc[ju] : -1;
    __syncthreads();
    int j = bj*256 + tid;
    if (j >= nv) return;
    int my = g_sidc[j];
    int lim = (bu < bj) ? 256 : tid;
    int r = 0;
    for (int u = 0; u < lim; u++) r += (sp[u] == my);
    if (r) atomicAdd(&g_rs[j], r);
}
__global__ void sscat_k(){
    int j = blockIdx.x*256 + threadIdx.x;
    if (j >= g_nvalid) return;
    g_slist[g_soff[g_sidc[j]] + g_rs[j]] = j;
}

__global__ void avg_k(const float* __restrict__ pe){
    int j = blockIdx.x;
    int nv = g_nvalid;
    if (j >= nv){
        __nv_bfloat16 zb = __float2bfloat16(0.f);
        for (int c = threadIdx.x; c < HD; c += 256){
            g_kah[j*HD+c]=zb; g_kal[j*HD+c]=zb; g_vah[j*HD+c]=zb; g_val[j*HD+c]=zb;
        }
        return;
    }
    int m = g_vlist[j];
    int c0 = g_boff[m], c1 = g_boff[m+1];
    float dn = 1.0f / (float)max(c1 - c0, 1);
    for (int c = threadIdx.x; c < HD; c += 256){
        float sk = 0.f, sv = 0.f;
        for (int i = c0; i < c1; i++){
            int t = g_bperm[i];
            sk += g_kf[t*HD + c] + pe[g_pei[t] + c];
            sv += g_vf[t*HD + c];
        }
        sk *= dn; sv *= dn;
        __nv_bfloat16 kh = __float2bfloat16(sk);
        __nv_bfloat16 vh = __float2bfloat16(sv);
        g_kah[j*HD+c] = kh; g_kal[j*HD+c] = __float2bfloat16(sk - __bfloat162float(kh));
        g_vah[j*HD+c] = vh; g_val[j*HD+c] = __float2bfloat16(sv - __bfloat162float(vh));
    }
    if (threadIdx.x == 0){
        int mx = m >> 8, my = (m >> 4) & 15, mz = m & 15;
        g_sidc[j] = ((mx>>1)<<6) | ((my>>1)<<3) | (mz>>1);
        atomicAdd(&g_scount[g_sidc[j]], 1);
    }
}
__global__ void cvt_k(){
    __shared__ float t[32][33];
    int bj = blockIdx.x*32, bd = blockIdx.y*32;
    int tx = threadIdx.x & 31, ty = threadIdx.x >> 5;
    for (int r = ty; r < 32; r += 8) t[r][tx] = g_cv[(size_t)(bj+r)*HD + bd + tx];
    __syncthreads();
    for (int r = ty; r < 32; r += 8){
        int gd = bd + r, h = gd >> 6, dd = gd & 63;
        float x = t[tx][r];
        __nv_bfloat16 hb = __float2bfloat16(x);
        g_cvth[(size_t)(h*DH + dd)*MB + bj + tx] = hb;
        g_cvtl[(size_t)(h*DH + dd)*MB + bj + tx] = __float2bfloat16(x - __bfloat162float(hb));
    }
}

// ---------------- mma.sync stage compute: 8 warps, CTA tile 128x128 ----------------
#define KSTR 24
#define ARR  6144
#define STG  24576
#define MMSM (2*STG)

__device__ __forceinline__ void mma_stage(unsigned base, int wm, int wn, int lane, float acc[4][4][4]){
    unsigned ah[4][4], al[4][4], bh[4][2], bl[4][2];
    int t7 = lane & 7, t8 = lane >> 3;
    #pragma unroll
    for (int mt = 0; mt < 4; mt++){
        int m = wm*64 + mt*16 + (t8&1)*8 + t7;
        unsigned off = base + (m*KSTR + (t8>>1)*8)*2;
        ldsm4(ah[mt], off);
        ldsm4(al[mt], off + ARR);
    }
    #pragma unroll
    for (int p = 0; p < 2; p++){
        int n = wn*32 + p*16 + (t8>>1)*8 + t7;
        unsigned off = base + 2*ARR + (n*KSTR + (t8&1)*8)*2;
        unsigned r[4];
        ldsm4(r, off);
        bh[2*p][0]=r[0]; bh[2*p][1]=r[1]; bh[2*p+1][0]=r[2]; bh[2*p+1][1]=r[3];
        ldsm4(r, off + ARR);
        bl[2*p][0]=r[0]; bl[2*p][1]=r[1]; bl[2*p+1][0]=r[2]; bl[2*p+1][1]=r[3];
    }
    #pragma unroll
    for (int mt = 0; mt < 4; mt++)
        #pragma unroll
        for (int nt = 0; nt < 4; nt++){
            mma16816(acc[mt][nt], ah[mt], bh[nt]);
            mma16816(acc[mt][nt], ah[mt], bl[nt]);
            mma16816(acc[mt][nt], al[mt], bh[nt]);
        }
}

// ---------------- GEMM A[·,512] x W^T -> C[128,128] tiles (reg-prefetch, R11) ----------------
__global__ void __launch_bounds__(256) mm_k(
    const __nv_bfloat16* __restrict__ Ah0, const __nv_bfloat16* __restrict__ Al0,
    const __nv_bfloat16* __restrict__ Ah1, const __nv_bfloat16* __restrict__ Al1,
    int wbase, float* C0, float* C1, float* C2,
    __nv_bfloat16* Hh, __nv_bfloat16* Hl, float hscale, int hz0, int guard)
{
    extern __shared__ char smem[];
    int z = blockIdx.z;
    const __nv_bfloat16* Ah = (z==1) ? Ah1 : Ah0;
    const __nv_bfloat16* Al = (z==1) ? Al1 : Al0;
    const __nv_bfloat16* Bh = g_wth + (size_t)(wbase+z)*HD*HD;
    const __nv_bfloat16* Bl = g_wtl + (size_t)(wbase+z)*HD*HD;
    float* C = (z==0) ? C0 : ((z==1) ? C1 : C2);
    int tbm = blockIdx.y*128, tbn = blockIdx.x*128;
    if (guard && tbm >= g_nvalid) return;
    unsigned s0 = smem_u32(smem);
    int tid = threadIdx.x, lane = tid & 31, warp = tid >> 5;
    int wm = warp & 1, wn = warp >> 1;
    int row = tid >> 1, half = tid & 1;
    size_t aoff = (size_t)(tbm+row)*HD + half*8;
    size_t boff = (size_t)(tbn+row)*HD + half*8;
    unsigned sdst = (row*KSTR + half*8)*2;

    float acc[4][4][4];
    #pragma unroll
    for (int i = 0; i < 4; i++)
        #pragma unroll
        for (int j2 = 0; j2 < 4; j2++){ acc[i][j2][0]=0.f; acc[i][j2][1]=0.f; acc[i][j2][2]=0.f; acc[i][j2][3]=0.f; }

    float4 pa = *(const float4*)&Ah[aoff];
    float4 pl = *(const float4*)&Al[aoff];
    float4 pb = *(const float4*)&Bh[boff];
    float4 pq = *(const float4*)&Bl[boff];
    { unsigned b = s0 + sdst; sts128(b, pa); sts128(b+ARR, pl); sts128(b+2*ARR, pb); sts128(b+3*ARR, pq); }
    __syncthreads();
    for (int it = 1; it <= 32; it++){
        if (it < 32){
            pa = *(const float4*)&Ah[aoff + it*16];
            pl = *(const float4*)&Al[aoff + it*16];
            pb = *(const float4*)&Bh[boff + it*16];
            pq = *(const float4*)&Bl[boff + it*16];
        }
        mma_stage(s0 + ((it-1)&1)*STG, wm, wn, lane, acc);
        if (it < 32){
            unsigned b = s0 + (it&1)*STG + sdst;
            sts128(b, pa); sts128(b+ARR, pl); sts128(b+2*ARR, pb); sts128(b+3*ARR, pq);
            __syncthreads();
        }
    }
    #pragma unroll
    for (int mt = 0; mt < 4; mt++){
        int m0 = tbm + wm*64 + mt*16 + (lane>>2);
        #pragma unroll
        for (int nt = 0; nt < 4; nt++){
            int n = tbn + wn*32 + nt*8 + (lane&3)*2;
            float* c = acc[mt][nt];
            size_t i0 = (size_t)m0*HD + n, i1 = (size_t)(m0+8)*HD + n;
            *(float2*)&C[i0] = make_float2(c[0], c[1]);
            *(float2*)&C[i1] = make_float2(c[2], c[3]);
            if (hz0 && z == 0){
                float s0v = c[0]*hscale, s1v = c[1]*hscale, s2v = c[2]*hscale, s3v = c[3]*hscale;
                __nv_bfloat16 h0 = __float2bfloat16(s0v), h1 = __float2bfloat16(s1v);
                __nv_bfloat16 h2 = __float2bfloat16(s2v), h3 = __float2bfloat16(s3v);
                *(__nv_bfloat162*)&Hh[i0] = __nv_bfloat162(h0, h1);
                *(__nv_bfloat162*)&Hh[i1] = __nv_bfloat162(h2, h3);
                *(__nv_bfloat162*)&Hl[i0] = __nv_bfloat162(
                    __float2bfloat16(s0v-__bfloat162float(h0)), __float2bfloat16(s1v-__bfloat162float(h1)));
                *(__nv_bfloat162*)&Hl[i1] = __nv_bfloat162(
                    __float2bfloat16(s2v-__bfloat162float(h2)), __float2bfloat16(s3v-__bfloat162float(h3)));
            }
        }
    }
}

// ---------------- fused flash compressed attention ----------------
#define QPL  18432
#define KVPL 9216
#define KVST 18432
#define FASM (36864 + 36864 + 36864)

__global__ void __launch_bounds__(256) fa_k(){
    extern __shared__ char smem[];
    unsigned s0 = smem_u32(smem);
    unsigned Kb = s0 + 36864, Vb = s0 + 73728;
    int h = blockIdx.y, nt = blockIdx.x*128;
    int nv = g_nvalid;
    int njt = (nv + 63) >> 6;
    int tid = threadIdx.x, lane = tid & 31, w = tid >> 5;
    int tg = lane & 3, gp = lane >> 2;
    int t7 = lane & 7, t8 = lane >> 3;

    #pragma unroll
    for (int q = 0; q < 8; q++){
        int jb = tid + 256*q, pl = jb >> 10, rem = jb & 1023, row = rem >> 3, c8 = rem & 7;
        const __nv_bfloat16* src = pl ? g_ql : g_qh;
        float4 v = *(const float4*)&src[(size_t)(nt+row)*HD + h*DH + c8*8];
        sts128(s0 + pl*QPL + (row*72 + c8*8)*2, v);
    }
    __syncthreads();
    unsigned aqh[4][4], aql[4][4];
    #pragma unroll
    for (int kc = 0; kc < 4; kc++){
        unsigned off = ((w*16 + (t8&1)*8 + t7)*72 + kc*16 + (t8>>1)*8)*2;
        ldsm4(aqh[kc], s0 + off);
        ldsm4(aql[kc], s0 + QPL + off);
    }

    float m0 = -3.0e38f, m1 = -3.0e38f, l0 = 0.f, l1 = 0.f;
    float co[8][4];
    #pragma unroll
    for (int i = 0; i < 8; i++){ co[i][0]=0.f; co[i][1]=0.f; co[i][2]=0.f; co[i][3]=0.f; }

    float4 kr[4], vr[4];
    #pragma unroll
    for (int q = 0; q < 4; q++){
        int jb = tid + 256*q, pl = jb >> 9, rem = jb & 511, row = rem >> 3, c8 = rem & 7;
        const __nv_bfloat16* ks = pl ? g_ckl : g_ckh;
        kr[q] = *(const float4*)&ks[(size_t)row*HD + h*DH + c8*8];
        const __nv_bfloat16* vs = pl ? g_cvtl : g_cvth;
        vr[q] = *(const float4*)&vs[(size_t)(h*DH+row)*MB + c8*8];
    }
    #pragma unroll
    for (int q = 0; q < 4; q++){
        int jb = tid + 256*q, pl = jb >> 9, rem = jb & 511, row = rem >> 3, c8 = rem & 7;
        unsigned off = pl*KVPL + (row*72 + c8*8)*2;
        sts128(Kb + off, kr[q]);
        sts128(Vb + off, vr[q]);
    }
    __syncthreads();

    for (int t = 0; t < njt; t++){
        if (t+1 < njt){
            int j0 = (t+1)*64;
            #pragma unroll
            for (int q = 0; q < 4; q++){
                int jb = tid + 256*q, pl = jb >> 9, rem = jb & 511, row = rem >> 3, c8 = rem & 7;
                const __nv_bfloat16* ks = pl ? g_ckl : g_ckh;
                kr[q] = *(const float4*)&ks[(size_t)(j0+row)*HD + h*DH + c8*8];
                const __nv_bfloat16* vs = pl ? g_cvtl : g_cvth;
                vr[q] = *(const float4*)&vs[(size_t)(h*DH+row)*MB + j0 + c8*8];
            }
        }
        int st = t & 1;
        float cs[8][4];
        #pragma unroll
        for (int i = 0; i < 8; i++){ cs[i][0]=0.f; cs[i][1]=0.f; cs[i][2]=0.f; cs[i][3]=0.f; }
        #pragma unroll
        for (int kc = 0; kc < 4; kc++){
            unsigned bh[8][2], bl[8][2];
            #pragma unroll
            for (int p = 0; p < 4; p++){
                unsigned off = Kb + st*KVST + ((p*16 + (t8>>1)*8 + t7)*72 + kc*16 + (t8&1)*8)*2;
                unsigned r[4];
                ldsm4(r, off);
                bh[2*p][0]=r[0]; bh[2*p][1]=r[1]; bh[2*p+1][0]=r[2]; bh[2*p+1][1]=r[3];
                ldsm4(r, off + KVPL);
                bl[2*p][0]=r[0]; bl[2*p][1]=r[1]; bl[2*p+1][0]=r[2]; bl[2*p+1][1]=r[3];
            }
            #pragma unroll
            for (int n8 = 0; n8 < 8; n8++){
                mma16816(cs[n8], aqh[kc], bh[n8]);
                mma16816(cs[n8], aqh[kc], bl[n8]);
                mma16816(cs[n8], aql[kc], bh[n8]);
            }
        }
        int jb0 = t*64 + tg*2;
        float tm0 = -3.0e38f, tm1 = -3.0e38f;
        #pragma unroll
        for (int n8 = 0; n8 < 8; n8++){
            int j = jb0 + n8*8;
            if (j   >= nv){ cs[n8][0] = -3.0e38f; cs[n8][2] = -3.0e38f; }
            if (j+1 >= nv){ cs[n8][1] = -3.0e38f; cs[n8][3] = -3.0e38f; }
            tm0 = fmaxf(tm0, fmaxf(cs[n8][0], cs[n8][1]));
            tm1 = fmaxf(tm1, fmaxf(cs[n8][2], cs[n8][3]));
        }
        tm0 = fmaxf(tm0, __shfl_xor_sync(0xffffffffu, tm0, 1));
        tm0 = fmaxf(tm0, __shfl_xor_sync(0xffffffffu, tm0, 2));
        tm1 = fmaxf(tm1, __shfl_xor_sync(0xffffffffu, tm1, 1));
        tm1 = fmaxf(tm1, __shfl_xor_sync(0xffffffffu, tm1, 2));
        float nm0 = fmaxf(m0, tm0), nm1 = fmaxf(m1, tm1);
        float f0 = fexp(m0 - nm0), f1 = fexp(m1 - nm1);
        m0 = nm0; m1 = nm1;
        l0 *= f0; l1 *= f1;
        #pragma unroll
        for (int d8 = 0; d8 < 8; d8++){
            co[d8][0] *= f0; co[d8][1] *= f0; co[d8][2] *= f1; co[d8][3] *= f1;
        }
        unsigned pah[4][4], pal[4][4];
        #pragma unroll
        for (int kc = 0; kc < 4; kc++){
            float e00 = fexp(cs[2*kc][0] - m0),   e01 = fexp(cs[2*kc][1] - m0);
            float e02 = fexp(cs[2*kc][2] - m1),   e03 = fexp(cs[2*kc][3] - m1);
            float e10 = fexp(cs[2*kc+1][0] - m0), e11 = fexp(cs[2*kc+1][1] - m0);
            float e12 = fexp(cs[2*kc+1][2] - m1), e13 = fexp(cs[2*kc+1][3] - m1);
            l0 += e00 + e01 + e10 + e11;
            l1 += e02 + e03 + e12 + e13;
            __nv_bfloat16 h00=__float2bfloat16(e00), h01=__float2bfloat16(e01);
            __nv_bfloat16 h02=__float2bfloat16(e02), h03=__float2bfloat16(e03);
            __nv_bfloat16 h10=__float2bfloat16(e10), h11=__float2bfloat16(e11);
            __nv_bfloat16 h12=__float2bfloat16(e12), h13=__float2bfloat16(e13);
            pah[kc][0] = pack2(h00, h01);
            pah[kc][1] = pack2(h02, h03);
            pah[kc][2] = pack2(h10, h11);
            pah[kc][3] = pack2(h12, h13);
            pal[kc][0] = pack2(__float2bfloat16(e00-__bfloat162float(h00)), __float2bfloat16(e01-__bfloat162float(h01)));
            pal[kc][1] = pack2(__float2bfloat16(e02-__bfloat162float(h02)), __float2bfloat16(e03-__bfloat162float(h03)));
            pal[kc][2] = pack2(__float2bfloat16(e10-__bfloat162float(h10)), __float2bfloat16(e11-__bfloat162float(h11)));
            pal[kc][3] = pack2(__float2bfloat16(e12-__bfloat162float(h12)), __float2bfloat16(e13-__bfloat162float(h13)));
        }
        #pragma unroll
        for (int kc = 0; kc < 4; kc++){
            unsigned bh[8][2], bl[8][2];
            #pragma unroll
            for (int p = 0; p < 4; p++){
                unsigned off = Vb + st*KVST + ((p*16 + (t8>>1)*8 + t7)*72 + kc*16 + (t8&1)*8)*2;
                unsigned r[4];
                ldsm4(r, off);
                bh[2*p][0]=r[0]; bh[2*p][1]=r[1]; bh[2*p+1][0]=r[2]; bh[2*p+1][1]=r[3];
                ldsm4(r, off + KVPL);
                bl[2*p][0]=r[0]; bl[2*p][1]=r[1]; bl[2*p+1][0]=r[2]; bl[2*p+1][1]=r[3];
            }
            #pragma unroll
            for (int d8 = 0; d8 < 8; d8++){
                mma16816(co[d8], pah[kc], bh[d8]);
                mma16816(co[d8], pah[kc], bl[d8]);
                mma16816(co[d8], pal[kc], bh[d8]);
            }
        }
        if (t+1 < njt){
            int nst = (t+1) & 1;
            #pragma unroll
            for (int q = 0; q < 4; q++){
                int jb = tid + 256*q, pl = jb >> 9, rem = jb & 511, row = rem >> 3, c8 = rem & 7;
                unsigned off = pl*KVPL + (row*72 + c8*8)*2;
                sts128(Kb + nst*KVST + off, kr[q]);
                sts128(Vb + nst*KVST + off, vr[q]);
            }
            __syncthreads();
        }
    }
    l0 += __shfl_xor_sync(0xffffffffu, l0, 1);
    l0 += __shfl_xor_sync(0xffffffffu, l0, 2);
    l1 += __shfl_xor_sync(0xffffffffu, l1, 1);
    l1 += __shfl_xor_sync(0xffffffffu, l1, 2);
    float iv0 = 1.0f / l0, iv1 = 1.0f / l1;
    int row0 = nt + w*16 + gp;
    if (tg == 0){
        g_invl[h*NTOK + row0]     = iv0;
        g_invl[h*NTOK + row0 + 8] = iv1;
        g_rowm[h*NTOK + row0]     = m0;
        g_rowm[h*NTOK + row0 + 8] = m1;
    }
    #pragma unroll
    for (int d8 = 0; d8 < 8; d8++){
        int col = h*DH + d8*8 + tg*2;
        *(float2*)&g_outc[(size_t)row0*HD + col]     = make_float2(co[d8][0]*iv0, co[d8][1]*iv0);
        *(float2*)&g_outc[(size_t)(row0+8)*HD + col] = make_float2(co[d8][2]*iv1, co[d8][3]*iv1);
    }
}

// ---------------- P8: recompute S per head (R11 reg-staged) ----------------
#define P8SM (36864 + 36864)

__global__ void __launch_bounds__(256) p8_k(){
    extern __shared__ char smem[];
    unsigned s0 = smem_u32(smem);
    unsigned Kb = s0 + 36864;
    int ntb = blockIdx.x*128, jt = blockIdx.y*128;
    int nv = g_nvalid;
    if (jt >= nv) return;
    int tid = threadIdx.x, lane = tid & 31, w = tid >> 5;
    int tg = lane & 3, gp = lane >> 2;
    int t7 = lane & 7, t8 = lane >> 3;
    int row0 = ntb + w*16 + gp;

    float acc[16][4];
    #pragma unroll
    for (int i = 0; i < 16; i++){ acc[i][0]=0.f; acc[i][1]=0.f; acc[i][2]=0.f; acc[i][3]=0.f; }

    for (int h = 0; h < NH; h++){
        float4 qr[8], kr[8];
        #pragma unroll
        for (int q = 0; q < 8; q++){
            int jb = tid + 256*q, pl = jb >> 10, rem = jb & 1023, row = rem >> 3, c8 = rem & 7;
            const __nv_bfloat16* qs = pl ? g_ql  : g_qh;
            qr[q] = *(const float4*)&qs[(size_t)(ntb+row)*HD + h*DH + c8*8];
            const __nv_bfloat16* ks = pl ? g_ckl : g_ckh;
            kr[q] = *(const float4*)&ks[(size_t)(jt+row)*HD + h*DH + c8*8];
        }
        __syncthreads();
        #pragma unroll
        for (int q = 0; q < 8; q++){
            int jb = tid + 256*q, pl = jb >> 10, rem = jb & 1023, row = rem >> 3, c8 = rem & 7;
            unsigned off = pl*QPL + (row*72 + c8*8)*2;
            sts128(s0 + off, qr[q]);
            sts128(Kb + off, kr[q]);
        }
        __syncthreads();
        unsigned aqh[4][4], aql[4][4];
        #pragma unroll
        for (int kc = 0; kc < 4; kc++){
            unsigned off = ((w*16 + (t8&1)*8 + t7)*72 + kc*16 + (t8>>1)*8)*2;
            ldsm4(aqh[kc], s0 + off);
            ldsm4(aql[kc], s0 + QPL + off);
        }
        float cs[16][4];
        #pragma unroll
        for (int i = 0; i < 16; i++){ cs[i][0]=0.f; cs[i][1]=0.f; cs[i][2]=0.f; cs[i][3]=0.f; }
        #pragma unroll
        for (int kc = 0; kc < 4; kc++){
            unsigned bh[16][2], bl[16][2];
            #pragma unroll
            for (int p = 0; p < 8; p++){
                unsigned off = Kb + ((p*16 + (t8>>1)*8 + t7)*72 + kc*16 + (t8&1)*8)*2;
                unsigned r[4];
                ldsm4(r, off);
                bh[2*p][0]=r[0]; bh[2*p][1]=r[1]; bh[2*p+1][0]=r[2]; bh[2*p+1][1]=r[3];
                ldsm4(r, off + QPL);
                bl[2*p][0]=r[0]; bl[2*p][1]=r[1]; bl[2*p+1][0]=r[2]; bl[2*p+1][1]=r[3];
            }
            #pragma unroll
            for (int n8 = 0; n8 < 16; n8++){
                mma16816(cs[n8], aqh[kc], bh[n8]);
                mma16816(cs[n8], aqh[kc], bl[n8]);
                mma16816(cs[n8], aql[kc], bh[n8]);
            }
        }
        float m0 = g_rowm[h*NTOK + row0],     iv0 = g_invl[h*NTOK + row0];
        float m1 = g_rowm[h*NTOK + row0 + 8], iv1 = g_invl[h*NTOK + row0 + 8];
        #pragma unroll
        for (int n8 = 0; n8 < 16; n8++){
            int j = jt + n8*8 + tg*2;
            if (j < nv){
                acc[n8][0] += fexp(cs[n8][0] - m0) * iv0;
                acc[n8][2] += fexp(cs[n8][2] - m1) * iv1;
            }
            if (j+1 < nv){
                acc[n8][1] += fexp(cs[n8][1] - m0) * iv0;
                acc[n8][3] += fexp(cs[n8][3] - m1) * iv1;
            }
        }
    }
    #pragma unroll
    for (int n8 = 0; n8 < 16; n8++){
        int j = jt + n8*8 + tg*2;
        *(float2*)&g_P8[(size_t)row0*MB + j]     = make_float2(acc[n8][0], acc[n8][1]);
        *(float2*)&g_P8[(size_t)(row0+8)*MB + j] = make_float2(acc[n8][2], acc[n8][3]);
    }
}

// ---------------- merged top-8 + selection/window attention ----------------
__global__ void tsp_k(){
    int n = blockIdx.x, tid = threadIdx.x;
    int lane = tid & 31, w = tid >> 5;
    __shared__ float ss[SBN];
    __shared__ float wv[16];
    __shared__ int   wi[16];
    __shared__ int   t8s[8];
    float v = 0.f;
    int o0 = g_soff[tid], o1 = g_soff[tid+1];
    for (int i = o0; i < o1; i++) v += g_P8[(size_t)n*MB + g_slist[i]];
    ss[tid] = v;
    __syncthreads();
    for (int r = 0; r < 8; r++){
        float mv = ss[tid]; int mi = tid;
        #pragma unroll
        for (int o = 16; o; o >>= 1){
            float ov = __shfl_xor_sync(0xffffffffu, mv, o);
            int   oi = __shfl_xor_sync(0xffffffffu, mi, o);
            if (ov > mv || (ov == mv && oi < mi)){ mv = ov; mi = oi; }
        }
        if (lane == 0){ wv[w] = mv; wi[w] = mi; }
        __syncthreads();
        if (tid < 16){
            float m2 = wv[tid]; int i2 = wi[tid];
            #pragma unroll
            for (int o = 8; o; o >>= 1){
                float ov = __shfl_xor_sync(0x0000ffffu, m2, o);
                int   oi = __shfl_xor_sync(0x0000ffffu, i2, o);
                if (ov > m2 || (ov == m2 && oi < i2)){ m2 = ov; i2 = oi; }
            }
            if (tid == 0){ t8s[r] = i2; ss[i2] = -1e30f; }
        }
        __syncthreads();
    }
    int mode = w >> 3, h = w & 7;
    const float* qr = &g_q[n*HD + h*DH];
    float q0 = qr[lane], q1 = qr[lane + 32];
    float m = -1e30f, l = 0.f, a0 = 0.f, a1 = 0.f;
    int nb = (mode == 0) ? 8 : 1;
    for (int kk = 0; kk < nb; kk++){
        int b, o, e;
        if (mode == 0){ b = t8s[kk];  o = g_sboff[b]; e = g_sboff[b+1]; }
        else          { b = g_wid[n]; o = g_woff[b];  e = g_woff[b+1]; }
        for (int i = o; i < e; i++){
            int t = (mode == 0) ? g_sbperm[i] : g_wperm[i];
            const float* kr = &g_kf[t*HD + h*DH];
            float s = q0*kr[lane] + q1*kr[lane + 32];
            #pragma unroll
            for (int of = 16; of; of >>= 1) s += __shfl_xor_sync(0xffffffffu, s, of);
            s *= 0.125f;
            float mn = fmaxf(m, s);
            float c = fexp(m - mn), ww = fexp(s - mn);
            const float* vr = &g_vf[t*HD + h*DH];
            l  = l*c  + ww;
            a0 = a0*c + ww*vr[lane];
            a1 = a1*c + ww*vr[lane + 32];
            m = mn;
        }
    }
    float* outp = mode ? g_outw : g_outs;
    outp[n*HD + h*DH + lane]      = a0 / l;
    outp[n*HD + h*DH + lane + 32] = a1 / l;
}

// ---------------- gated fuse -> split bf16 ----------------
__global__ void fuse_k(){
    int i = blockIdx.x*256 + threadIdx.x;
    int n = i >> 9;
    float g0 = g_gate[n*3+0], g1 = g_gate[n*3+1], g2 = g_gate[n*3+2];
    float v = g0*g_outc[i] + g1*g_outs[i] + g2*g_outw[i];
    __nv_bfloat16 hb = __float2bfloat16(v);
    g_fh[i] = hb;
    g_fl[i] = __float2bfloat16(v - __bfloat162float(hb));
}

// ---------------- launch ----------------
extern "C" void kernel_launch(void* const* d_in, const int* in_sizes, int n_in,
                              void* d_out, int out_size){
    const float* feats  = (const float*)d_in[0];
    const int*   coords = (const int*)  d_in[1];
    const float* Wq  = (const float*)d_in[2];
    const float* Wk  = (const float*)d_in[3];
    const float* Wv  = (const float*)d_in[4];
    const float* Wo  = (const float*)d_in[5];
    const float* Wck = (const float*)d_in[6];
    const float* Wcv = (const float*)d_in[7];
    const float* pe  = (const float*)d_in[8];
    const float* Wg  = (const float*)d_in[9];
    float* out = (float*)d_out;

    float *gq, *gkf, *gvf, *gck, *gcv;
    __nv_bfloat16 *fh, *fl, *qh, *ql, *kah, *kal, *vah, *val, *ckh, *ckl;
    cudaGetSymbolAddress((void**)&gq,  g_q);
    cudaGetSymbolAddress((void**)&gkf, g_kf);
    cudaGetSymbolAddress((void**)&gvf, g_vf);
    cudaGetSymbolAddress((void**)&gck, g_ck);
    cudaGetSymbolAddress((void**)&gcv, g_cv);
    cudaGetSymbolAddress((void**)&fh,  g_fh);
    cudaGetSymbolAddress((void**)&fl,  g_fl);
    cudaGetSymbolAddress((void**)&qh,  g_qh);
    cudaGetSymbolAddress((void**)&ql,  g_ql);
    cudaGetSymbolAddress((void**)&kah, g_kah);
    cudaGetSymbolAddress((void**)&kal, g_kal);
    cudaGetSymbolAddress((void**)&vah, g_vah);
    cudaGetSymbolAddress((void**)&val, g_val);
    cudaGetSymbolAddress((void**)&ckh, g_ckh);
    cudaGetSymbolAddress((void**)&ckl, g_ckl);

    cudaFuncSetAttribute(mm_k, cudaFuncAttributeMaxDynamicSharedMemorySize, MMSM);
    cudaFuncSetAttribute(fa_k, cudaFuncAttributeMaxDynamicSharedMemorySize, FASM);
    cudaFuncSetAttribute(p8_k, cudaFuncAttributeMaxDynamicSharedMemorySize, P8SM);

    zero_k<<<64, 256>>>();
    prep_k<<<8, 256>>>(coords);
    init2_k<<<6656, 256>>>(feats, Wq, Wk, Wv, Wck, Wcv, Wo, Wg);

    mm_k<<<dim3(4, NTOK/128, 3), 256, MMSM>>>(fh, fl, fh, fl, 0, gq, gkf, gvf, qh, ql, 0.125f, 1, 0);

    scan1_k<<<1, 128>>>();
    permcnt_k<<<dim3(8, 8), 256>>>();
    permscat_k<<<8, 256>>>();
    avg_k<<<MB, 256>>>(pe);

    mm_k<<<dim3(4, MB/128, 2), 256, MMSM>>>(kah, kal, vah, val, 3, gck, gcv, gcv, ckh, ckl, 1.0f, 1, 1);
    cvt_k<<<dim3(MB/32, HD/32), 256>>>();

    scan2_k<<<1, 32>>>();
    scnt_k<<<dim3(8, 8), 256>>>();
    sscat_k<<<8, 256>>>();

    fa_k<<<dim3(NTOK/128, NH), 256, FASM>>>();
    p8_k<<<dim3(NTOK/128, 13), 256, P8SM>>>();
    tsp_k<<<NTOK, 512>>>();
    fuse_k<<<NTOK*HD/256, 256>>>();

    mm_k<<<dim3(4, NTOK/128, 1), 256, MMSM>>>(fh, fl, fh, fl, 5, out, out, out, qh, ql, 1.0f, 0, 0);
}

// round 14
// speedup vs baseline: 1.1722x; 1.1440x over previous
#include <cuda_runtime.h>
#include <cuda_bf16.h>

#define NTOK 2048
#define HD   512
#define NH   8
#define DH   64
#define MB   4096
#define SBN  512
#define NWID 729

// ---------------- scratch ----------------
__device__ float g_q[NTOK*HD], g_kf[NTOK*HD], g_vf[NTOK*HD];
__device__ float g_ck[MB*HD], g_cv[MB*HD];
__device__ float g_P8[(size_t)NTOK*MB];
__device__ float g_invl[NH*NTOK];
__device__ float g_rowm[NH*NTOK];
__device__ float g_outc[NTOK*HD], g_outs[NTOK*HD], g_outw[NTOK*HD];
__device__ float g_gate[NTOK*3];
__device__ int g_cnt[MB], g_boff[MB+1], g_bperm[NTOK], g_bid[NTOK];
__device__ int g_sbcnt[SBN], g_sboff[SBN+1], g_sbperm[NTOK], g_sbid[NTOK];
__device__ int g_wcnt[NWID], g_woff[NWID+1], g_wperm[NTOK], g_wid[NTOK];
__device__ int g_scount[SBN], g_soff[SBN+1], g_slist[MB], g_sidc[MB];
__device__ int g_vlist[MB], g_nvalid;
__device__ int g_pei[NTOK], g_packed[NTOK], g_top8[NTOK*8];
__device__ int g_r1[NTOK], g_r2[NTOK], g_r3[NTOK], g_rs[MB];
// split-bf16 operands
__device__ __nv_bfloat16 g_wth[6*HD*HD], g_wtl[6*HD*HD];
__device__ __nv_bfloat16 g_fh[NTOK*HD], g_fl[NTOK*HD];
__device__ __nv_bfloat16 g_qh[NTOK*HD], g_ql[NTOK*HD];   // pre-scaled by 0.125
__device__ __nv_bfloat16 g_kah[MB*HD], g_kal[MB*HD], g_vah[MB*HD], g_val[MB*HD];
__device__ __nv_bfloat16 g_ckh[MB*HD], g_ckl[MB*HD];
__device__ __nv_bfloat16 g_cvth[NH*DH*MB], g_cvtl[NH*DH*MB];

// ---------------- helpers ----------------
__device__ __forceinline__ unsigned smem_u32(const void* p){
    unsigned a;
    asm("{ .reg .u64 t; cvta.to.shared.u64 t, %1; cvt.u32.u64 %0, t; }" : "=r"(a) : "l"(p));
    return a;
}
__device__ __forceinline__ void sts128(unsigned a, float4 v){
    asm volatile("st.shared.v4.b32 [%0], {%1,%2,%3,%4};" :: "r"(a),
        "r"(__float_as_uint(v.x)), "r"(__float_as_uint(v.y)),
        "r"(__float_as_uint(v.z)), "r"(__float_as_uint(v.w)) : "memory");
}
__device__ __forceinline__ void ldsm4(unsigned* r, unsigned addr){
    asm volatile("ldmatrix.sync.aligned.m8n8.x4.shared.b16 {%0,%1,%2,%3}, [%4];"
        : "=r"(r[0]), "=r"(r[1]), "=r"(r[2]), "=r"(r[3]) : "r"(addr));
}
__device__ __forceinline__ void mma16816(float* c, const unsigned* a, const unsigned* b){
    asm volatile("mma.sync.aligned.m16n8k16.row.col.f32.bf16.bf16.f32 "
        "{%0,%1,%2,%3}, {%4,%5,%6,%7}, {%8,%9}, {%0,%1,%2,%3};"
        : "+f"(c[0]), "+f"(c[1]), "+f"(c[2]), "+f"(c[3])
        : "r"(a[0]), "r"(a[1]), "r"(a[2]), "r"(a[3]), "r"(b[0]), "r"(b[1]));
}
__device__ __forceinline__ float fexp(float x){
    x = fminf(fmaxf(x, -87.0f), 88.0f);
    float y = x * 1.4426950408889634f;
    float z = y + 12582912.0f;
    int ki = __float_as_int(z) - 0x4B400000;
    float f = y - (z - 12582912.0f);
    float p = 1.5403530393381609e-4f;
    p = fmaf(p, f, 1.3333558146428443e-3f);
    p = fmaf(p, f, 9.6181291076284772e-3f);
    p = fmaf(p, f, 5.5504108664821580e-2f);
    p = fmaf(p, f, 2.4022650695910071e-1f);
    p = fmaf(p, f, 6.9314718055994531e-1f);
    p = fmaf(p, f, 1.0f);
    return __int_as_float((ki + 127) << 23) * p;
}
__device__ __forceinline__ unsigned pack2(__nv_bfloat16 a, __nv_bfloat16 b){
    return ((unsigned)__bfloat16_as_ushort(b) << 16) | __bfloat16_as_ushort(a);
}

// ---------------- setup ----------------
__global__ void zero_k(){
    int i = blockIdx.x*256 + threadIdx.x;
    if (i < MB){ g_cnt[i] = 0; g_rs[i] = 0; }
    if (i < SBN){ g_sbcnt[i] = 0; g_scount[i] = 0; }
    if (i < NWID) g_wcnt[i] = 0;
    if (i < NTOK){ g_r1[i] = 0; g_r2[i] = 0; g_r3[i] = 0; }
}
__global__ void prep_k(const int* __restrict__ coords){
    int t = blockIdx.x*256 + threadIdx.x;
    if (t >= NTOK) return;
    int cf = coords[t];
    int x = cf >> 12, y = (cf >> 6) & 63, z = cf & 63;
    int bid = ((x>>2)<<8) | ((y>>2)<<4) | (z>>2);
    g_bid[t] = bid; atomicAdd(&g_cnt[bid], 1);
    int sb = ((x>>3)<<6) | ((y>>3)<<3) | (z>>3);
    g_sbid[t] = sb; atomicAdd(&g_sbcnt[sb], 1);
    int wd = (((x+4)>>3)*9 + ((y+4)>>3))*9 + ((z+4)>>3);
    g_wid[t] = wd; atomicAdd(&g_wcnt[wd], 1);
    g_pei[t] = (((x&3)*4 + (y&3))*4 + (z&3)) * HD;
    g_packed[t] = bid | (sb << 12) | (wd << 21);
}
__global__ void gate_k(const float* __restrict__ feats, const float* __restrict__ Wg){
    int n = blockIdx.x;
    int w = threadIdx.x >> 5, lane = threadIdx.x & 31;
    if (w >= 3) return;
    float s = 0.f;
    for (int i = lane; i < HD; i += 32) s += feats[n*HD + i] * Wg[i*3 + w];
    #pragma unroll
    for (int o = 16; o; o >>= 1) s += __shfl_xor_sync(0xffffffffu, s, o);
    if (lane == 0) g_gate[n*3 + w] = 1.0f / (1.0f + fexp(-s));
}
__device__ __forceinline__ void warp_exscan(const int* cnt, int* off, int len){
    int lane = threadIdx.x & 31;
    int run = 0;
    for (int base = 0; base < len; base += 32){
        int raw = (base+lane < len) ? cnt[base+lane] : 0;
        int v = raw;
        #pragma unroll
        for (int o = 1; o < 32; o <<= 1){ int t = __shfl_up_sync(0xffffffffu, v, o); if (lane >= o) v += t; }
        if (base+lane < len) off[base+lane] = run + v - raw;
        run += __shfl_sync(0xffffffffu, v, 31);
    }
    if (lane == 0) off[len] = run;
}
__global__ void scan1_k(){
    int w = threadIdx.x >> 5;
    if (w == 0) warp_exscan(g_cnt, g_boff, MB);
    else if (w == 1) warp_exscan(g_sbcnt, g_sboff, SBN);
    else if (w == 2) warp_exscan(g_wcnt, g_woff, NWID);
    else {
        int lane = threadIdx.x & 31;
        int run = 0;
        for (int base = 0; base < MB; base += 32){
            int valid = g_cnt[base+lane] > 0 ? 1 : 0;
            int v = valid;
            #pragma unroll
            for (int o = 1; o < 32; o <<= 1){ int t = __shfl_up_sync(0xffffffffu, v, o); if (lane >= o) v += t; }
            if (valid) g_vlist[run + v - 1] = base + lane;
            run += __shfl_sync(0xffffffffu, v, 31);
        }
        if (lane == 0) g_nvalid = run;
    }
}
__global__ void scan2_k(){ warp_exscan(g_scount, g_soff, SBN); }

__global__ void permcnt_k(){
    int bt = blockIdx.x, bu = blockIdx.y;
    if (bu > bt) return;
    __shared__ int sp[256];
    int tid = threadIdx.x;
    int t = bt*256 + tid;
    sp[tid] = g_packed[bu*256 + tid];
    __syncthreads();
    int my = g_packed[t];
    int lim = (bu < bt) ? 256 : tid;
    int r1 = 0, r2 = 0, r3 = 0;
    for (int u = 0; u < lim; u++){
        int p = sp[u] ^ my;
        r3 += ((p & 0x00000FFF) == 0);
        r1 += ((p & 0x001FF000) == 0);
        r2 += ((p & 0x7FE00000) == 0);
    }
    if (r1) atomicAdd(&g_r1[t], r1);
    if (r2) atomicAdd(&g_r2[t], r2);
    if (r3) atomicAdd(&g_r3[t], r3);
}
__global__ void permscat_k(){
    int t = blockIdx.x*256 + threadIdx.x;
    if (t >= NTOK) return;
    int my = g_packed[t];
    int bd = my & 0xFFF, sb = (my >> 12) & 0x1FF, wd = (my >> 21) & 0x3FF;
    g_sbperm[g_sboff[sb] + g_r1[t]] = t;
    g_wperm [g_woff[wd]  + g_r2[t]] = t;
    g_bperm [g_boff[bd]  + g_r3[t]] = t;
}
__global__ void scnt_k(){
    int bj = blockIdx.x, bu = blockIdx.y;
    if (bu > bj) return;
    __shared__ int sp[256];
    int tid = threadIdx.x;
    int nv = g_nvalid;
    int ju = bu*256 + tid;
    sp[tid] = (ju < nv) ? g_sidc[ju] : -1;
    __syncthreads();
    int j = bj*256 + tid;
    if (j >= nv) return;
    int my = g_sidc[j];
    int lim = (bu < bj) ? 256 : tid;
    int r = 0;
    for (int u = 0; u < lim; u++) r += (sp[u] == my);
    if (r) atomicAdd(&g_rs[j], r);
}
__global__ void sscat_k(){
    int j = blockIdx.x*256 + threadIdx.x;
    if (j >= g_nvalid) return;
    g_slist[g_soff[g_sidc[j]] + g_rs[j]] = j;
}

__global__ void avg_k(const float* __restrict__ pe){
    int j = blockIdx.x;
    int nv = g_nvalid;
    if (j >= nv){
        __nv_bfloat16 zb = __float2bfloat16(0.f);
        for (int c = threadIdx.x; c < HD; c += 256){
            g_kah[j*HD+c]=zb; g_kal[j*HD+c]=zb; g_vah[j*HD+c]=zb; g_val[j*HD+c]=zb;
        }
        return;
    }
    int m = g_vlist[j];
    int c0 = g_boff[m], c1 = g_boff[m+1];
    float dn = 1.0f / (float)max(c1 - c0, 1);
    for (int c = threadIdx.x; c < HD; c += 256){
        float sk = 0.f, sv = 0.f;
        for (int i = c0; i < c1; i++){
            int t = g_bperm[i];
            sk += g_kf[t*HD + c] + pe[g_pei[t] + c];
            sv += g_vf[t*HD + c];
        }
        sk *= dn; sv *= dn;
        __nv_bfloat16 kh = __float2bfloat16(sk);
        __nv_bfloat16 vh = __float2bfloat16(sv);
        g_kah[j*HD+c] = kh; g_kal[j*HD+c] = __float2bfloat16(sk - __bfloat162float(kh));
        g_vah[j*HD+c] = vh; g_val[j*HD+c] = __float2bfloat16(sv - __bfloat162float(vh));
    }
    if (threadIdx.x == 0){
        int mx = m >> 8, my = (m >> 4) & 15, mz = m & 15;
        g_sidc[j] = ((mx>>1)<<6) | ((my>>1)<<3) | (mz>>1);
        atomicAdd(&g_scount[g_sidc[j]], 1);
    }
}
__global__ void convA_k(const float* __restrict__ in, __nv_bfloat16* __restrict__ h, __nv_bfloat16* __restrict__ l){
    int i = blockIdx.x*256 + threadIdx.x;
    float x = in[i];
    __nv_bfloat16 hb = __float2bfloat16(x);
    h[i] = hb; l[i] = __float2bfloat16(x - __bfloat162float(hb));
}
__global__ void convW_k(const float* W0, const float* W1, const float* W2,
                        const float* W3, const float* W4, const float* W5){
    int z = blockIdx.z;
    const float* W = z==0?W0 : z==1?W1 : z==2?W2 : z==3?W3 : z==4?W4 : W5;
    __nv_bfloat16* h = g_wth + (size_t)z*HD*HD;
    __nv_bfloat16* l = g_wtl + (size_t)z*HD*HD;
    __shared__ float t[32][33];
    int bn = blockIdx.x*32, bk = blockIdx.y*32;
    int tx = threadIdx.x & 31, ty = threadIdx.x >> 5;
    for (int r = ty; r < 32; r += 8) t[r][tx] = W[(size_t)(bk+r)*HD + bn + tx];
    __syncthreads();
    for (int r = ty; r < 32; r += 8){
        float x = t[tx][r];
        __nv_bfloat16 hb = __float2bfloat16(x);
        h[(size_t)(bn+r)*HD + bk + tx] = hb;
        l[(size_t)(bn+r)*HD + bk + tx] = __float2bfloat16(x - __bfloat162float(hb));
    }
}
__global__ void cvt_k(){
    __shared__ float t[32][33];
    int bj = blockIdx.x*32, bd = blockIdx.y*32;
    int tx = threadIdx.x & 31, ty = threadIdx.x >> 5;
    for (int r = ty; r < 32; r += 8) t[r][tx] = g_cv[(size_t)(bj+r)*HD + bd + tx];
    __syncthreads();
    for (int r = ty; r < 32; r += 8){
        int gd = bd + r, h = gd >> 6, dd = gd & 63;
        float x = t[tx][r];
        __nv_bfloat16 hb = __float2bfloat16(x);
        g_cvth[(size_t)(h*DH + dd)*MB + bj + tx] = hb;
        g_cvtl[(size_t)(h*DH + dd)*MB + bj + tx] = __float2bfloat16(x - __bfloat162float(hb));
    }
}

// ---------------- mma.sync stage compute: 8 warps, CTA tile 128x128 ----------------
#define KSTR 24
#define ARR  6144
#define STG  24576
#define MMSM (2*STG)

__device__ __forceinline__ void mma_stage(unsigned base, int wm, int wn, int lane, float acc[4][4][4]){
    unsigned ah[4][4], al[4][4], bh[4][2], bl[4][2];
    int t7 = lane & 7, t8 = lane >> 3;
    #pragma unroll
    for (int mt = 0; mt < 4; mt++){
        int m = wm*64 + mt*16 + (t8&1)*8 + t7;
        unsigned off = base + (m*KSTR + (t8>>1)*8)*2;
        ldsm4(ah[mt], off);
        ldsm4(al[mt], off + ARR);
    }
    #pragma unroll
    for (int p = 0; p < 2; p++){
        int n = wn*32 + p*16 + (t8>>1)*8 + t7;
        unsigned off = base + 2*ARR + (n*KSTR + (t8&1)*8)*2;
        unsigned r[4];
        ldsm4(r, off);
        bh[2*p][0]=r[0]; bh[2*p][1]=r[1]; bh[2*p+1][0]=r[2]; bh[2*p+1][1]=r[3];
        ldsm4(r, off + ARR);
        bl[2*p][0]=r[0]; bl[2*p][1]=r[1]; bl[2*p+1][0]=r[2]; bl[2*p+1][1]=r[3];
    }
    #pragma unroll
    for (int mt = 0; mt < 4; mt++)
        #pragma unroll
        for (int nt = 0; nt < 4; nt++){
            mma16816(acc[mt][nt], ah[mt], bh[nt]);
            mma16816(acc[mt][nt], ah[mt], bl[nt]);
            mma16816(acc[mt][nt], al[mt], bh[nt]);
        }
}

// ---------------- GEMM A[·,512] x W^T -> C[128,128] tiles ----------------
__global__ void __launch_bounds__(256) mm_k(
    const __nv_bfloat16* __restrict__ Ah0, const __nv_bfloat16* __restrict__ Al0,
    const __nv_bfloat16* __restrict__ Ah1, const __nv_bfloat16* __restrict__ Al1,
    int wbase, float* C0, float* C1, float* C2,
    __nv_bfloat16* Hh, __nv_bfloat16* Hl, float hscale, int hz0, int guard)
{
    extern __shared__ char smem[];
    int z = blockIdx.z;
    const __nv_bfloat16* Ah = (z==1) ? Ah1 : Ah0;
    const __nv_bfloat16* Al = (z==1) ? Al1 : Al0;
    const __nv_bfloat16* Bh = g_wth + (size_t)(wbase+z)*HD*HD;
    const __nv_bfloat16* Bl = g_wtl + (size_t)(wbase+z)*HD*HD;
    float* C = (z==0) ? C0 : ((z==1) ? C1 : C2);
    int tbm = blockIdx.y*128, tbn = blockIdx.x*128;
    if (guard && tbm >= g_nvalid) return;
    unsigned s0 = smem_u32(smem);
    int tid = threadIdx.x, lane = tid & 31, warp = tid >> 5;
    int wm = warp & 1, wn = warp >> 1;
    int row = tid >> 1, half = tid & 1;
    size_t aoff = (size_t)(tbm+row)*HD + half*8;
    size_t boff = (size_t)(tbn+row)*HD + half*8;
    unsigned sdst = (row*KSTR + half*8)*2;

    float acc[4][4][4];
    #pragma unroll
    for (int i = 0; i < 4; i++)
        #pragma unroll
        for (int j2 = 0; j2 < 4; j2++){ acc[i][j2][0]=0.f; acc[i][j2][1]=0.f; acc[i][j2][2]=0.f; acc[i][j2][3]=0.f; }

    float4 pa = *(const float4*)&Ah[aoff];
    float4 pl = *(const float4*)&Al[aoff];
    float4 pb = *(const float4*)&Bh[boff];
    float4 pq = *(const float4*)&Bl[boff];
    { unsigned b = s0 + sdst; sts128(b, pa); sts128(b+ARR, pl); sts128(b+2*ARR, pb); sts128(b+3*ARR, pq); }
    __syncthreads();
    for (int it = 1; it <= 32; it++){
        if (it < 32){
            pa = *(const float4*)&Ah[aoff + it*16];
            pl = *(const float4*)&Al[aoff + it*16];
            pb = *(const float4*)&Bh[boff + it*16];
            pq = *(const float4*)&Bl[boff + it*16];
        }
        mma_stage(s0 + ((it-1)&1)*STG, wm, wn, lane, acc);
        if (it < 32){
            unsigned b = s0 + (it&1)*STG + sdst;
            sts128(b, pa); sts128(b+ARR, pl); sts128(b+2*ARR, pb); sts128(b+3*ARR, pq);
            __syncthreads();
        }
    }
    #pragma unroll
    for (int mt = 0; mt < 4; mt++){
        int m0 = tbm + wm*64 + mt*16 + (lane>>2);
        #pragma unroll
        for (int nt = 0; nt < 4; nt++){
            int n = tbn + wn*32 + nt*8 + (lane&3)*2;
            float* c = acc[mt][nt];
            size_t i0 = (size_t)m0*HD + n, i1 = (size_t)(m0+8)*HD + n;
            *(float2*)&C[i0] = make_float2(c[0], c[1]);
            *(float2*)&C[i1] = make_float2(c[2], c[3]);
            if (hz0 && z == 0){
                float s0v = c[0]*hscale, s1v = c[1]*hscale, s2v = c[2]*hscale, s3v = c[3]*hscale;
                __nv_bfloat16 h0 = __float2bfloat16(s0v), h1 = __float2bfloat16(s1v);
                __nv_bfloat16 h2 = __float2bfloat16(s2v), h3 = __float2bfloat16(s3v);
                *(__nv_bfloat162*)&Hh[i0] = __nv_bfloat162(h0, h1);
                *(__nv_bfloat162*)&Hh[i1] = __nv_bfloat162(h2, h3);
                *(__nv_bfloat162*)&Hl[i0] = __nv_bfloat162(
                    __float2bfloat16(s0v-__bfloat162float(h0)), __float2bfloat16(s1v-__bfloat162float(h1)));
                *(__nv_bfloat162*)&Hl[i1] = __nv_bfloat162(
                    __float2bfloat16(s2v-__bfloat162float(h2)), __float2bfloat16(s3v-__bfloat162float(h3)));
            }
        }
    }
}

// ---------------- fused flash compressed attention ----------------
#define QPL  18432
#define KVPL 9216
#define KVST 18432
#define FASM (36864 + 36864 + 36864)

__global__ void __launch_bounds__(256) fa_k(){
    extern __shared__ char smem[];
    unsigned s0 = smem_u32(smem);
    unsigned Kb = s0 + 36864, Vb = s0 + 73728;
    int h = blockIdx.y, nt = blockIdx.x*128;
    int nv = g_nvalid;
    int njt = (nv + 63) >> 6;
    int tid = threadIdx.x, lane = tid & 31, w = tid >> 5;
    int tg = lane & 3, gp = lane >> 2;
    int t7 = lane & 7, t8 = lane >> 3;

    #pragma unroll
    for (int q = 0; q < 8; q++){
        int jb = tid + 256*q, pl = jb >> 10, rem = jb & 1023, row = rem >> 3, c8 = rem & 7;
        const __nv_bfloat16* src = pl ? g_ql : g_qh;
        float4 v = *(const float4*)&src[(size_t)(nt+row)*HD + h*DH + c8*8];
        sts128(s0 + pl*QPL + (row*72 + c8*8)*2, v);
    }
    __syncthreads();
    unsigned aqh[4][4], aql[4][4];
    #pragma unroll
    for (int kc = 0; kc < 4; kc++){
        unsigned off = ((w*16 + (t8&1)*8 + t7)*72 + kc*16 + (t8>>1)*8)*2;
        ldsm4(aqh[kc], s0 + off);
        ldsm4(aql[kc], s0 + QPL + off);
    }

    float m0 = -3.0e38f, m1 = -3.0e38f, l0 = 0.f, l1 = 0.f;
    float co[8][4];
    #pragma unroll
    for (int i = 0; i < 8; i++){ co[i][0]=0.f; co[i][1]=0.f; co[i][2]=0.f; co[i][3]=0.f; }

    float4 kr[4], vr[4];
    #pragma unroll
    for (int q = 0; q < 4; q++){
        int jb = tid + 256*q, pl = jb >> 9, rem = jb & 511, row = rem >> 3, c8 = rem & 7;
        const __nv_bfloat16* ks = pl ? g_ckl : g_ckh;
        kr[q] = *(const float4*)&ks[(size_t)row*HD + h*DH + c8*8];
        const __nv_bfloat16* vs = pl ? g_cvtl : g_cvth;
        vr[q] = *(const float4*)&vs[(size_t)(h*DH+row)*MB + c8*8];
    }
    #pragma unroll
    for (int q = 0; q < 4; q++){
        int jb = tid + 256*q, pl = jb >> 9, rem = jb & 511, row = rem >> 3, c8 = rem & 7;
        unsigned off = pl*KVPL + (row*72 + c8*8)*2;
        sts128(Kb + off, kr[q]);
        sts128(Vb + off, vr[q]);
    }
    __syncthreads();

    for (int t = 0; t < njt; t++){
        if (t+1 < njt){
            int j0 = (t+1)*64;
            #pragma unroll
            for (int q = 0; q < 4; q++){
                int jb = tid + 256*q, pl = jb >> 9, rem = jb & 511, row = rem >> 3, c8 = rem & 7;
                const __nv_bfloat16* ks = pl ? g_ckl : g_ckh;
                kr[q] = *(const float4*)&ks[(size_t)(j0+row)*HD + h*DH + c8*8];
                const __nv_bfloat16* vs = pl ? g_cvtl : g_cvth;
                vr[q] = *(const float4*)&vs[(size_t)(h*DH+row)*MB + j0 + c8*8];
            }
        }
        int st = t & 1;
        float cs[8][4];
        #pragma unroll
        for (int i = 0; i < 8; i++){ cs[i][0]=0.f; cs[i][1]=0.f; cs[i][2]=0.f; cs[i][3]=0.f; }
        #pragma unroll
        for (int kc = 0; kc < 4; kc++){
            unsigned bh[8][2], bl[8][2];
            #pragma unroll
            for (int p = 0; p < 4; p++){
                unsigned off = Kb + st*KVST + ((p*16 + (t8>>1)*8 + t7)*72 + kc*16 + (t8&1)*8)*2;
                unsigned r[4];
                ldsm4(r, off);
                bh[2*p][0]=r[0]; bh[2*p][1]=r[1]; bh[2*p+1][0]=r[2]; bh[2*p+1][1]=r[3];
                ldsm4(r, off + KVPL);
                bl[2*p][0]=r[0]; bl[2*p][1]=r[1]; bl[2*p+1][0]=r[2]; bl[2*p+1][1]=r[3];
            }
            #pragma unroll
            for (int n8 = 0; n8 < 8; n8++){
                mma16816(cs[n8], aqh[kc], bh[n8]);
                mma16816(cs[n8], aqh[kc], bl[n8]);
                mma16816(cs[n8], aql[kc], bh[n8]);
            }
        }
        int jb0 = t*64 + tg*2;
        float tm0 = -3.0e38f, tm1 = -3.0e38f;
        #pragma unroll
        for (int n8 = 0; n8 < 8; n8++){
            int j = jb0 + n8*8;
            if (j   >= nv){ cs[n8][0] = -3.0e38f; cs[n8][2] = -3.0e38f; }
            if (j+1 >= nv){ cs[n8][1] = -3.0e38f; cs[n8][3] = -3.0e38f; }
            tm0 = fmaxf(tm0, fmaxf(cs[n8][0], cs[n8][1]));
            tm1 = fmaxf(tm1, fmaxf(cs[n8][2], cs[n8][3]));
        }
        tm0 = fmaxf(tm0, __shfl_xor_sync(0xffffffffu, tm0, 1));
        tm0 = fmaxf(tm0, __shfl_xor_sync(0xffffffffu, tm0, 2));
        tm1 = fmaxf(tm1, __shfl_xor_sync(0xffffffffu, tm1, 1));
        tm1 = fmaxf(tm1, __shfl_xor_sync(0xffffffffu, tm1, 2));
        float nm0 = fmaxf(m0, tm0), nm1 = fmaxf(m1, tm1);
        float f0 = fexp(m0 - nm0), f1 = fexp(m1 - nm1);
        m0 = nm0; m1 = nm1;
        l0 *= f0; l1 *= f1;
        #pragma unroll
        for (int d8 = 0; d8 < 8; d8++){
            co[d8][0] *= f0; co[d8][1] *= f0; co[d8][2] *= f1; co[d8][3] *= f1;
        }
        unsigned pah[4][4], pal[4][4];
        #pragma unroll
        for (int kc = 0; kc < 4; kc++){
            float e00 = fexp(cs[2*kc][0] - m0),   e01 = fexp(cs[2*kc][1] - m0);
            float e02 = fexp(cs[2*kc][2] - m1),   e03 = fexp(cs[2*kc][3] - m1);
            float e10 = fexp(cs[2*kc+1][0] - m0), e11 = fexp(cs[2*kc+1][1] - m0);
            float e12 = fexp(cs[2*kc+1][2] - m1), e13 = fexp(cs[2*kc+1][3] - m1);
            l0 += e00 + e01 + e10 + e11;
            l1 += e02 + e03 + e12 + e13;
            __nv_bfloat16 h00=__float2bfloat16(e00), h01=__float2bfloat16(e01);
            __nv_bfloat16 h02=__float2bfloat16(e02), h03=__float2bfloat16(e03);
            __nv_bfloat16 h10=__float2bfloat16(e10), h11=__float2bfloat16(e11);
            __nv_bfloat16 h12=__float2bfloat16(e12), h13=__float2bfloat16(e13);
            pah[kc][0] = pack2(h00, h01);
            pah[kc][1] = pack2(h02, h03);
            pah[kc][2] = pack2(h10, h11);
            pah[kc][3] = pack2(h12, h13);
            pal[kc][0] = pack2(__float2bfloat16(e00-__bfloat162float(h00)), __float2bfloat16(e01-__bfloat162float(h01)));
            pal[kc][1] = pack2(__float2bfloat16(e02-__bfloat162float(h02)), __float2bfloat16(e03-__bfloat162float(h03)));
            pal[kc][2] = pack2(__float2bfloat16(e10-__bfloat162float(h10)), __float2bfloat16(e11-__bfloat162float(h11)));
            pal[kc][3] = pack2(__float2bfloat16(e12-__bfloat162float(h12)), __float2bfloat16(e13-__bfloat162float(h13)));
        }
        #pragma unroll
        for (int kc = 0; kc < 4; kc++){
            unsigned bh[8][2], bl[8][2];
            #pragma unroll
            for (int p = 0; p < 4; p++){
                unsigned off = Vb + st*KVST + ((p*16 + (t8>>1)*8 + t7)*72 + kc*16 + (t8&1)*8)*2;
                unsigned r[4];
                ldsm4(r, off);
                bh[2*p][0]=r[0]; bh[2*p][1]=r[1]; bh[2*p+1][0]=r[2]; bh[2*p+1][1]=r[3];
                ldsm4(r, off + KVPL);
                bl[2*p][0]=r[0]; bl[2*p][1]=r[1]; bl[2*p+1][0]=r[2]; bl[2*p+1][1]=r[3];
            }
            #pragma unroll
            for (int d8 = 0; d8 < 8; d8++){
                mma16816(co[d8], pah[kc], bh[d8]);
                mma16816(co[d8], pah[kc], bl[d8]);
                mma16816(co[d8], pal[kc], bh[d8]);
            }
        }
        if (t+1 < njt){
            int nst = (t+1) & 1;
            #pragma unroll
            for (int q = 0; q < 4; q++){
                int jb = tid + 256*q, pl = jb >> 9, rem = jb & 511, row = rem >> 3, c8 = rem & 7;
                unsigned off = pl*KVPL + (row*72 + c8*8)*2;
                sts128(Kb + nst*KVST + off, kr[q]);
                sts128(Vb + nst*KVST + off, vr[q]);
            }
            __syncthreads();
        }
    }
    l0 += __shfl_xor_sync(0xffffffffu, l0, 1);
    l0 += __shfl_xor_sync(0xffffffffu, l0, 2);
    l1 += __shfl_xor_sync(0xffffffffu, l1, 1);
    l1 += __shfl_xor_sync(0xffffffffu, l1, 2);
    float iv0 = 1.0f / l0, iv1 = 1.0f / l1;
    int row0 = nt + w*16 + gp;
    if (tg == 0){
        g_invl[h*NTOK + row0]     = iv0;
        g_invl[h*NTOK + row0 + 8] = iv1;
        g_rowm[h*NTOK + row0]     = m0;
        g_rowm[h*NTOK + row0 + 8] = m1;
    }
    #pragma unroll
    for (int d8 = 0; d8 < 8; d8++){
        int col = h*DH + d8*8 + tg*2;
        *(float2*)&g_outc[(size_t)row0*HD + col]     = make_float2(co[d8][0]*iv0, co[d8][1]*iv0);
        *(float2*)&g_outc[(size_t)(row0+8)*HD + col] = make_float2(co[d8][2]*iv1, co[d8][3]*iv1);
    }
}

// ---------------- P8: recompute S per head, sum exp(s-m)*invl over heads ----------------
#define P8SM (36864 + 36864)

__global__ void __launch_bounds__(256) p8_k(){
    extern __shared__ char smem[];
    unsigned s0 = smem_u32(smem);
    unsigned Kb = s0 + 36864;
    int ntb = blockIdx.x*128, jt = blockIdx.y*128;
    int nv = g_nvalid;
    if (jt >= nv) return;
    int tid = threadIdx.x, lane = tid & 31, w = tid >> 5;
    int tg = lane & 3, gp = lane >> 2;
    int t7 = lane & 7, t8 = lane >> 3;
    int row0 = ntb + w*16 + gp;

    float acc[16][4];
    #pragma unroll
    for (int i = 0; i < 16; i++){ acc[i][0]=0.f; acc[i][1]=0.f; acc[i][2]=0.f; acc[i][3]=0.f; }

    for (int h = 0; h < NH; h++){
        float4 qr[8], kr[8];
        #pragma unroll
        for (int q = 0; q < 8; q++){
            int jb = tid + 256*q, pl = jb >> 10, rem = jb & 1023, row = rem >> 3, c8 = rem & 7;
            const __nv_bfloat16* qs = pl ? g_ql  : g_qh;
            qr[q] = *(const float4*)&qs[(size_t)(ntb+row)*HD + h*DH + c8*8];
            const __nv_bfloat16* ks = pl ? g_ckl : g_ckh;
            kr[q] = *(const float4*)&ks[(size_t)(jt+row)*HD + h*DH + c8*8];
        }
        __syncthreads();
        #pragma unroll
        for (int q = 0; q < 8; q++){
            int jb = tid + 256*q, pl = jb >> 10, rem = jb & 1023, row = rem >> 3, c8 = rem & 7;
            unsigned off = pl*QPL + (row*72 + c8*8)*2;
            sts128(s0 + off, qr[q]);
            sts128(Kb + off, kr[q]);
        }
        __syncthreads();
        unsigned aqh[4][4], aql[4][4];
        #pragma unroll
        for (int kc = 0; kc < 4; kc++){
            unsigned off = ((w*16 + (t8&1)*8 + t7)*72 + kc*16 + (t8>>1)*8)*2;
            ldsm4(aqh[kc], s0 + off);
            ldsm4(aql[kc], s0 + QPL + off);
        }
        float cs[16][4];
        #pragma unroll
        for (int i = 0; i < 16; i++){ cs[i][0]=0.f; cs[i][1]=0.f; cs[i][2]=0.f; cs[i][3]=0.f; }
        #pragma unroll
        for (int kc = 0; kc < 4; kc++){
            unsigned bh[16][2], bl[16][2];
            #pragma unroll
            for (int p = 0; p < 8; p++){
                unsigned off = Kb + ((p*16 + (t8>>1)*8 + t7)*72 + kc*16 + (t8&1)*8)*2;
                unsigned r[4];
                ldsm4(r, off);
                bh[2*p][0]=r[0]; bh[2*p][1]=r[1]; bh[2*p+1][0]=r[2]; bh[2*p+1][1]=r[3];
                ldsm4(r, off + QPL);
                bl[2*p][0]=r[0]; bl[2*p][1]=r[1]; bl[2*p+1][0]=r[2]; bl[2*p+1][1]=r[3];
            }
            #pragma unroll
            for (int n8 = 0; n8 < 16; n8++){
                mma16816(cs[n8], aqh[kc], bh[n8]);
                mma16816(cs[n8], aqh[kc], bl[n8]);
                mma16816(cs[n8], aql[kc], bh[n8]);
            }
        }
        float m0 = g_rowm[h*NTOK + row0],     iv0 = g_invl[h*NTOK + row0];
        float m1 = g_rowm[h*NTOK + row0 + 8], iv1 = g_invl[h*NTOK + row0 + 8];
        #pragma unroll
        for (int n8 = 0; n8 < 16; n8++){
            int j = jt + n8*8 + tg*2;
            if (j < nv){
                acc[n8][0] += fexp(cs[n8][0] - m0) * iv0;
                acc[n8][2] += fexp(cs[n8][2] - m1) * iv1;
            }
            if (j+1 < nv){
                acc[n8][1] += fexp(cs[n8][1] - m0) * iv0;
                acc[n8][3] += fexp(cs[n8][3] - m1) * iv1;
            }
        }
    }
    #pragma unroll
    for (int n8 = 0; n8 < 16; n8++){
        int j = jt + n8*8 + tg*2;
        *(float2*)&g_P8[(size_t)row0*MB + j]     = make_float2(acc[n8][0], acc[n8][1]);
        *(float2*)&g_P8[(size_t)(row0+8)*MB + j] = make_float2(acc[n8][2], acc[n8][3]);
    }
}

// ---------------- sel_score + top-8 ----------------
__global__ void topk_k(){
    int n = blockIdx.x, tid = threadIdx.x;
    int lane = tid & 31, w = tid >> 5;
    __shared__ float ss[SBN];
    __shared__ float wv[16];
    __shared__ int   wi[16];
    float v = 0.f;
    int o0 = g_soff[tid], o1 = g_soff[tid+1];
    for (int i = o0; i < o1; i++) v += g_P8[(size_t)n*MB + g_slist[i]];
    ss[tid] = v;
    __syncthreads();
    for (int r = 0; r < 8; r++){
        float mv = ss[tid]; int mi = tid;
        #pragma unroll
        for (int o = 16; o; o >>= 1){
            float ov = __shfl_xor_sync(0xffffffffu, mv, o);
            int   oi = __shfl_xor_sync(0xffffffffu, mi, o);
            if (ov > mv || (ov == mv && oi < mi)){ mv = ov; mi = oi; }
        }
        if (lane == 0){ wv[w] = mv; wi[w] = mi; }
        __syncthreads();
        if (tid < 16){
            float m2 = wv[tid]; int i2 = wi[tid];
            #pragma unroll
            for (int o = 8; o; o >>= 1){
                float ov = __shfl_xor_sync(0x0000ffffu, m2, o);
                int   oi = __shfl_xor_sync(0x0000ffffu, i2, o);
                if (ov > m2 || (ov == m2 && oi < i2)){ m2 = ov; i2 = oi; }
            }
            if (tid == 0){ g_top8[n*8 + r] = i2; ss[i2] = -1e30f; }
        }
        __syncthreads();
    }
}

// ---------------- selection / window attention ----------------
__global__ void spattn_k(){
    int n = blockIdx.x, mode = blockIdx.y;
    int h = threadIdx.x >> 5, lane = threadIdx.x & 31;
    const float* qr = &g_q[n*HD + h*DH];
    float q0 = qr[lane], q1 = qr[lane + 32];
    float m = -1e30f, l = 0.f, a0 = 0.f, a1 = 0.f;
    int nb = (mode == 0) ? 8 : 1;
    for (int kk = 0; kk < nb; kk++){
        int b, o, e;
        if (mode == 0){ b = g_top8[n*8 + kk]; o = g_sboff[b]; e = g_sboff[b+1]; }
        else          { b = g_wid[n];         o = g_woff[b];  e = g_woff[b+1]; }
        for (int i = o; i < e; i++){
            int t = (mode == 0) ? g_sbperm[i] : g_wperm[i];
            const float* kr = &g_kf[t*HD + h*DH];
            float s = q0*kr[lane] + q1*kr[lane + 32];
            #pragma unroll
            for (int of = 16; of; of >>= 1) s += __shfl_xor_sync(0xffffffffu, s, of);
            s *= 0.125f;
            float mn = fmaxf(m, s);
            float c = fexp(m - mn), ww = fexp(s - mn);
            const float* vr = &g_vf[t*HD + h*DH];
            l  = l*c  + ww;
            a0 = a0*c + ww*vr[lane];
            a1 = a1*c + ww*vr[lane + 32];
            m = mn;
        }
    }
    float* outp = mode ? g_outw : g_outs;
    outp[n*HD + h*DH + lane]      = a0 / l;
    outp[n*HD + h*DH + lane + 32] = a1 / l;
}

// ---------------- gated fuse -> split bf16 (input to Wo GEMM) ----------------
__global__ void fuse_k(){
    int i = blockIdx.x*256 + threadIdx.x;
    int n = i >> 9;
    float g0 = g_gate[n*3+0], g1 = g_gate[n*3+1], g2 = g_gate[n*3+2];
    float v = g0*g_outc[i] + g1*g_outs[i] + g2*g_outw[i];
    __nv_bfloat16 hb = __float2bfloat16(v);
    g_fh[i] = hb;
    g_fl[i] = __float2bfloat16(v - __bfloat162float(hb));
}

// ---------------- launch ----------------
extern "C" void kernel_launch(void* const* d_in, const int* in_sizes, int n_in,
                              void* d_out, int out_size){
    const float* feats  = (const float*)d_in[0];
    const int*   coords = (const int*)  d_in[1];
    const float* Wq  = (const float*)d_in[2];
    const float* Wk  = (const float*)d_in[3];
    const float* Wv  = (const float*)d_in[4];
    const float* Wo  = (const float*)d_in[5];
    const float* Wck = (const float*)d_in[6];
    const float* Wcv = (const float*)d_in[7];
    const float* pe  = (const float*)d_in[8];
    const float* Wg  = (const float*)d_in[9];
    float* out = (float*)d_out;

    float *gq, *gkf, *gvf, *gck, *gcv;
    __nv_bfloat16 *fh, *fl, *qh, *ql, *kah, *kal, *vah, *val, *ckh, *ckl;
    cudaGetSymbolAddress((void**)&gq,  g_q);
    cudaGetSymbolAddress((void**)&gkf, g_kf);
    cudaGetSymbolAddress((void**)&gvf, g_vf);
    cudaGetSymbolAddress((void**)&gck, g_ck);
    cudaGetSymbolAddress((void**)&gcv, g_cv);
    cudaGetSymbolAddress((void**)&fh,  g_fh);
    cudaGetSymbolAddress((void**)&fl,  g_fl);
    cudaGetSymbolAddress((void**)&qh,  g_qh);
    cudaGetSymbolAddress((void**)&ql,  g_ql);
    cudaGetSymbolAddress((void**)&kah, g_kah);
    cudaGetSymbolAddress((void**)&kal, g_kal);
    cudaGetSymbolAddress((void**)&vah, g_vah);
    cudaGetSymbolAddress((void**)&val, g_val);
    cudaGetSymbolAddress((void**)&ckh, g_ckh);
    cudaGetSymbolAddress((void**)&ckl, g_ckl);

    cudaFuncSetAttribute(mm_k, cudaFuncAttributeMaxDynamicSharedMemorySize, MMSM);
    cudaFuncSetAttribute(fa_k, cudaFuncAttributeMaxDynamicSharedMemorySize, FASM);
    cudaFuncSetAttribute(p8_k, cudaFuncAttributeMaxDynamicSharedMemorySize, P8SM);

    zero_k<<<64, 256>>>();
    prep_k<<<8, 256>>>(coords);
    gate_k<<<NTOK, 128>>>(feats, Wg);
    convW_k<<<dim3(16, 16, 6), 256>>>(Wq, Wk, Wv, Wck, Wcv, Wo);
    convA_k<<<NTOK*HD/256, 256>>>(feats, fh, fl);

    // QKV projection: qh/ql emitted pre-scaled by 1/8
    mm_k<<<dim3(4, NTOK/128, 3), 256, MMSM>>>(fh, fl, fh, fl, 0, gq, gkf, gvf, qh, ql, 0.125f, 1, 0);

    scan1_k<<<1, 128>>>();
    permcnt_k<<<dim3(8, 8), 256>>>();
    permscat_k<<<8, 256>>>();
    avg_k<<<MB, 256>>>(pe);

    mm_k<<<dim3(4, MB/128, 2), 256, MMSM>>>(kah, kal, vah, val, 3, gck, gcv, gcv, ckh, ckl, 1.0f, 1, 1);
    cvt_k<<<dim3(MB/32, HD/32), 256>>>();

    scan2_k<<<1, 32>>>();
    scnt_k<<<dim3(8, 8), 256>>>();
    sscat_k<<<8, 256>>>();

    fa_k<<<dim3(NTOK/128, NH), 256, FASM>>>();
    p8_k<<<dim3(NTOK/128, 13), 256, P8SM>>>();
    topk_k<<<NTOK, 512>>>();
    spattn_k<<<dim3(NTOK, 2), 256>>>();
    fuse_k<<<NTOK*HD/256, 256>>>();

    mm_k<<<dim3(4, NTOK/128, 1), 256, MMSM>>>(fh, fl, fh, fl, 5, out, out, out, qh, ql, 1.0f, 0, 0);
}